// round 13
// baseline (speedup 1.0000x reference)
#include <cuda_runtime.h>
#include <cuda_fp16.h>
#include <math.h>
#include <stdint.h>

// Problem constants
#define B_  4
#define T_  2048
#define C_  1024
#define C3_ 3072
#define H_  16
#define HS_ 64
#define FF_ 4096
#define M_  (B_*T_)     // 8192 rows
#define EPS_ 1e-5f

// ---------------- scratch (no dynamic alloc allowed) ----------------
__device__ __half g_h   [M_*C_];    // LN output (half)
__device__ __half g_qkv [M_*C3_];   // fused q|k|v (half), row stride 3072
__device__ __half g_o   [M_*C_];    // attention output (half)
__device__ float  g_x1  [M_*C_];    // x + attn_out @ Wproj + bproj (fp32)
__device__ __half g_ff  [M_*FF_];   // relu(h2 @ W1 + b1) (half)
__device__ __half g_wqkv[C3_*C_];   // repacked+transposed [3C, C] qkv weight (half)
__device__ __half g_wp  [C_*C_];    // transposed Wproj [N,K] (half)
__device__ __half g_w1  [FF_*C_];   // transposed W1 [4096,1024] (half)
__device__ __half g_w2  [C_*FF_];   // transposed W2 [1024,4096] (half)

__device__ __forceinline__ uint32_t f2tf32(float f) {
    uint32_t u;
    asm("cvt.rna.tf32.f32 %0, %1;" : "=r"(u) : "f"(f));
    return u;
}
__device__ __forceinline__ float roundtf(float f) {
    return __uint_as_float(f2tf32(f));
}

// fp16 mma
__device__ __forceinline__ void mma_fp16(float* c, const uint32_t* a, const uint32_t* b) {
    asm volatile("mma.sync.aligned.m16n8k16.row.col.f32.f16.f16.f32 "
        "{%0,%1,%2,%3}, {%4,%5,%6,%7}, {%8,%9}, {%0,%1,%2,%3};"
        : "+f"(c[0]), "+f"(c[1]), "+f"(c[2]), "+f"(c[3])
        : "r"(a[0]), "r"(a[1]), "r"(a[2]), "r"(a[3]), "r"(b[0]), "r"(b[1]));
}
__device__ __forceinline__ void mma_fp16_2(float* c, const uint32_t* a,
                                           uint32_t b0, uint32_t b1) {
    asm volatile("mma.sync.aligned.m16n8k16.row.col.f32.f16.f16.f32 "
        "{%0,%1,%2,%3}, {%4,%5,%6,%7}, {%8,%9}, {%0,%1,%2,%3};"
        : "+f"(c[0]), "+f"(c[1]), "+f"(c[2]), "+f"(c[3])
        : "r"(a[0]), "r"(a[1]), "r"(a[2]), "r"(a[3]), "r"(b0), "r"(b1));
}
__device__ __forceinline__ void ldm_x4(uint32_t* r, uint32_t addr) {
    asm volatile("ldmatrix.sync.aligned.m8n8.x4.shared.b16 {%0,%1,%2,%3}, [%4];"
        : "=r"(r[0]), "=r"(r[1]), "=r"(r[2]), "=r"(r[3]) : "r"(addr));
}
__device__ __forceinline__ void ldm_x4_t(uint32_t* r, uint32_t addr) {
    asm volatile("ldmatrix.sync.aligned.m8n8.x4.trans.shared.b16 {%0,%1,%2,%3}, [%4];"
        : "=r"(r[0]), "=r"(r[1]), "=r"(r[2]), "=r"(r[3]) : "r"(addr));
}
__device__ __forceinline__ uint32_t smem_u32(const void* p) {
    return (uint32_t)__cvta_generic_to_shared(p);
}

// ---------------- LayerNorm: fp32 in, half out (warp-shuffle reduce) -------------
__global__ __launch_bounds__(256) void ln_kernel(const float* __restrict__ x,
                                                 const float* __restrict__ g,
                                                 const float* __restrict__ b,
                                                 __half* __restrict__ y)
{
    int row = blockIdx.x;
    const float* xr = x + (size_t)row * C_;
    __half* yr = y + (size_t)row * C_;
    int tid = threadIdx.x;
    int wid = tid >> 5, lane = tid & 31;

    float4 v = *(const float4*)(xr + tid * 4);
    float s  = v.x + v.y + v.z + v.w;
    float s2 = v.x * v.x + v.y * v.y + v.z * v.z + v.w * v.w;
    #pragma unroll
    for (int off = 16; off > 0; off >>= 1) {
        s  += __shfl_xor_sync(0xffffffffu, s,  off);
        s2 += __shfl_xor_sync(0xffffffffu, s2, off);
    }
    __shared__ float ws[8], ws2[8];
    if (lane == 0) { ws[wid] = s; ws2[wid] = s2; }
    __syncthreads();
    if (wid == 0) {
        float a  = (lane < 8) ? ws[lane]  : 0.f;
        float a2 = (lane < 8) ? ws2[lane] : 0.f;
        #pragma unroll
        for (int off = 4; off > 0; off >>= 1) {
            a  += __shfl_xor_sync(0xffffffffu, a,  off);
            a2 += __shfl_xor_sync(0xffffffffu, a2, off);
        }
        if (lane == 0) { ws[0] = a; ws2[0] = a2; }
    }
    __syncthreads();
    float mean = ws[0] * (1.0f / C_);
    float var  = ws2[0] * (1.0f / C_) - mean * mean;
    float rstd = rsqrtf(var + EPS_);

    const float4 gv = *(const float4*)(g + tid * 4);
    const float4 bv = *(const float4*)(b + tid * 4);
    __half2 h0 = __floats2half2_rn((v.x - mean) * rstd * gv.x + bv.x,
                                   (v.y - mean) * rstd * gv.y + bv.y);
    __half2 h1 = __floats2half2_rn((v.z - mean) * rstd * gv.z + bv.z,
                                   (v.w - mean) * rstd * gv.w + bv.w);
    *(__half2*)(yr + tid * 4)     = h0;
    *(__half2*)(yr + tid * 4 + 2) = h1;
}

// ---------------- repack [H,C,HS]x3 -> [3C, C] half ----------------
__global__ void repack_qkv3T(const float* __restrict__ Wq,
                             const float* __restrict__ Wk,
                             const float* __restrict__ Wv,
                             __half* __restrict__ Wt)
{
    int idx = blockIdx.x * 256 + threadIdx.x;   // idx = n*C + c
    if (idx < C3_*C_) {
        int n = idx >> 10;
        int c = idx & (C_ - 1);
        int sec = n >> 10;
        int nn = n & (C_ - 1);
        int h = nn >> 6;
        int d = nn & (HS_ - 1);
        const float* W = (sec == 0) ? Wq : (sec == 1) ? Wk : Wv;
        Wt[idx] = __float2half_rn(W[(size_t)h * C_ * HS_ + (size_t)c * HS_ + d]);
    }
}

// ---------------- transpose to half: src [R, Cc] fp32 -> dst [Cc, R] half -------
__global__ void transpose_h(const float* __restrict__ S, __half* __restrict__ D,
                            int R, int Cc)
{
    __shared__ float t[32][33];
    int bx = blockIdx.x * 32, by = blockIdx.y * 32;
    int x = threadIdx.x, y = threadIdx.y;
    #pragma unroll
    for (int i = 0; i < 32; i += 8)
        t[y + i][x] = S[(size_t)(by + y + i) * Cc + bx + x];
    __syncthreads();
    #pragma unroll
    for (int i = 0; i < 32; i += 8)
        D[(size_t)(bx + y + i) * R + by + x] = __float2half_rn(t[x][y + i]);
}

// ---------------- fp16 mma.sync GEMM, BK=64, 3-stage ----------------
// C[M,N] = A[M,K] @ Bt[N,K]^T  (+bias)(+res)(relu)
// out_mode: 0 = fp32, 1 = fp32 tf32-rounded, 2 = half
// 128x128 CTA tile, BK=64 halves, 8 warps at 64x32, 2 CTA/SM (2x110.6KB smem).
#define HSTR 72
#define HG_STAGE (2*128*HSTR)          // halves per stage (A+B) = 18432
#define HG_SMEM  (3*HG_STAGE*2)        // 110592 bytes

__global__ __launch_bounds__(256, 2) void gemm_fp16(const __half* __restrict__ A,
                                                    const __half* __restrict__ Bt,
                                                    void* __restrict__ Cm,
                                                    int Mn, int Nn, int Kn,
                                                    const float* __restrict__ bias,
                                                    const float* __restrict__ res,
                                                    int relu, int out_mode)
{
    extern __shared__ __half smh[];
    const int tid = threadIdx.x;
    const int wid = tid >> 5, lane = tid & 31;
    const int g = lane >> 2, tg = lane & 3;
    const int warp_m = wid >> 2;       // 0..1  (64 rows)
    const int warp_n = wid & 3;        // 0..3  (32 cols)
    const int bm = blockIdx.x * 128;
    const int bn = blockIdx.y * 128;

    const int a_row  = lane & 15;
    const int a_koff = (lane >> 4) << 3;
    const int b_row  = ((lane >> 4) << 3) + (lane & 7);
    const int b_koff = ((lane >> 3) & 1) << 3;

    float acc[4][4][4];
    #pragma unroll
    for (int mi = 0; mi < 4; mi++)
        #pragma unroll
        for (int ni = 0; ni < 4; ni++)
            #pragma unroll
            for (int r = 0; r < 4; r++) acc[mi][ni][r] = 0.f;

    auto fill = [&](int s, int kt) {
        const int k0 = kt << 6;
        __half* As = smh + s * HG_STAGE;
        __half* Bs = As + 128 * HSTR;
        #pragma unroll
        for (int i = 0; i < 4; i++) {
            int idx = tid + (i << 8);          // 1024 chunks of 16B per matrix
            int r = idx >> 3, c8 = (idx & 7) << 3;
            uint32_t da = smem_u32(As + r * HSTR + c8);
            asm volatile("cp.async.cg.shared.global [%0], [%1], 16;"
                         :: "r"(da), "l"(A + (size_t)(bm + r) * Kn + k0 + c8));
            uint32_t db = smem_u32(Bs + r * HSTR + c8);
            asm volatile("cp.async.cg.shared.global [%0], [%1], 16;"
                         :: "r"(db), "l"(Bt + (size_t)(bn + r) * Kn + k0 + c8));
        }
        asm volatile("cp.async.commit_group;");
    };

    const int KT = Kn >> 6;
    fill(0, 0);
    if (KT > 1) fill(1, 1);

    for (int kt = 0; kt < KT; kt++) {
        if (kt + 1 < KT) asm volatile("cp.async.wait_group 1;");
        else             asm volatile("cp.async.wait_group 0;");
        __syncthreads();
        if (kt + 2 < KT) fill((kt + 2) % 3, kt + 2);

        const __half* As = smh + (kt % 3) * HG_STAGE;
        const __half* Bs = As + 128 * HSTR;

        #pragma unroll
        for (int ks = 0; ks < 4; ks++) {
            const int kb0 = ks * 16;
            uint32_t af[4][4], bq[2][4];
            #pragma unroll
            for (int mi = 0; mi < 4; mi++)
                ldm_x4(af[mi], smem_u32(As + (warp_m * 64 + mi * 16 + a_row) * HSTR
                                           + kb0 + a_koff));
            #pragma unroll
            for (int np = 0; np < 2; np++)
                ldm_x4(bq[np], smem_u32(Bs + (warp_n * 32 + np * 16 + b_row) * HSTR
                                           + kb0 + b_koff));
            #pragma unroll
            for (int mi = 0; mi < 4; mi++)
                #pragma unroll
                for (int ni = 0; ni < 4; ni++)
                    mma_fp16(acc[mi][ni], af[mi], &bq[ni >> 1][(ni & 1) * 2]);
        }
        // no trailing sync: next iteration's top __syncthreads orders
        // this compute before fill(kt+2) overwrites a stage (3-deep ring).
    }

    #pragma unroll
    for (int mi = 0; mi < 4; mi++) {
        #pragma unroll
        for (int ni = 0; ni < 4; ni++) {
            int row0 = bm + warp_m * 64 + mi * 16 + g;
            int col  = bn + warp_n * 32 + ni * 8 + tg * 2;
            float bx = 0.f, by = 0.f;
            if (bias) { bx = bias[col]; by = bias[col + 1]; }
            #pragma unroll
            for (int half_ = 0; half_ < 2; half_++) {
                int row = row0 + half_ * 8;
                float v0 = acc[mi][ni][half_ * 2 + 0] + bx;
                float v1 = acc[mi][ni][half_ * 2 + 1] + by;
                if (res) {
                    const float* rp = res + (size_t)row * Nn + col;
                    v0 += rp[0]; v1 += rp[1];
                }
                if (relu) { v0 = fmaxf(v0, 0.f); v1 = fmaxf(v1, 0.f); }
                if (out_mode == 2) {
                    __half2 hv = __floats2half2_rn(v0, v1);
                    *(__half2*)((__half*)Cm + (size_t)row * Nn + col) = hv;
                } else {
                    if (out_mode == 1) { v0 = roundtf(v0); v1 = roundtf(v1); }
                    *(float2*)((float*)Cm + (size_t)row * Nn + col) = make_float2(v0, v1);
                }
            }
        }
    }
}

// ---------------- fp16 tensor-core flash attention (unchanged from R12) ---------
#define AKSTR 72
#define AQSTR 72
#define ATTN_SMEM ((4*64*AKSTR + 128*AQSTR)*2)   // 55296 bytes

__global__ __launch_bounds__(256, 2) void attn_h(const __half* __restrict__ qkv,
                                                 __half* __restrict__ o)
{
    extern __shared__ __half smha[];
    __half* Ks = smha;                    // 2 stages 64 x AKSTR
    __half* Vs = smha + 2*64*AKSTR;       // 2 stages 64 x AKSTR
    __half* Qs = Vs + 2*64*AKSTR;         // 128 x AQSTR (Q, pre-scaled)

    const int tid = threadIdx.x, wid = tid >> 5, lane = tid & 31;
    const int g = lane >> 2, tg = lane & 3;
    const int qt0 = blockIdx.x * 128;
    const int h = blockIdx.y, b = blockIdx.z;

    const __half* qbase = qkv + (size_t)(b * T_ + qt0) * C3_ + h * HS_;
    const __half* kbase = qkv + (size_t)b * T_ * C3_ + C_  + h * HS_;
    const __half* vbase = qkv + (size_t)b * T_ * C3_ + 2*C_ + h * HS_;

    // stage Q tile (128x64 half), pre-scaled by log2(e)/8
    {
        int r = tid >> 1, c = (tid & 1) * 32;
        const __half2 s8 = __float2half2_rn(0.1803368801f);   // log2(e)/8
        #pragma unroll
        for (int i = 0; i < 4; i++) {
            __half2 v[4];
            *(uint4*)v = *(const uint4*)(qbase + (size_t)r * C3_ + c + i * 8);
            #pragma unroll
            for (int j = 0; j < 4; j++) v[j] = __hmul2(v[j], s8);
            *(uint4*)(Qs + r * AQSTR + c + i * 8) = *(uint4*)v;
        }
    }

    const int m0 = wid * 16;
    const int r0 = qt0 + m0 + g;
    const int my_max = qt0 + m0 + 15;
    const int ntiles = (qt0 + 128) >> 6;
    const int lrow = lane & 15;
    const int lcol = (lane >> 4) << 3;
    const uint32_t ONE2 = 0x3C003C00u;    // half2(1, 1)

    auto loadKV = [&](int s, int s0) {
        const __half* kp = kbase + (size_t)s0 * C3_;
        const __half* vp = vbase + (size_t)s0 * C3_;
        __half* Kd = Ks + s * 64 * AKSTR;
        __half* Vd = Vs + s * 64 * AKSTR;
        #pragma unroll
        for (int i = 0; i < 2; i++) {
            int idx = tid + (i << 8);           // 512 chunks of 16B per matrix
            int r = idx >> 3, c8 = (idx & 7) * 8;
            uint32_t dk = smem_u32(Kd + r * AKSTR + c8);
            asm volatile("cp.async.cg.shared.global [%0], [%1], 16;"
                         :: "r"(dk), "l"(kp + (size_t)r * C3_ + c8));
            uint32_t dv = smem_u32(Vd + r * AKSTR + c8);
            asm volatile("cp.async.cg.shared.global [%0], [%1], 16;"
                         :: "r"(dv), "l"(vp + (size_t)r * C3_ + c8));
        }
        asm volatile("cp.async.commit_group;");
    };

    loadKV(0, 0);
    __syncthreads();      // Q staging visible

    uint32_t qf[4][4];
    #pragma unroll
    for (int kc = 0; kc < 4; kc++)
        ldm_x4(qf[kc], smem_u32(Qs + (m0 + lrow) * AQSTR + kc * 16 + lcol));

    float mrow0 = -INFINITY, mrow1 = -INFINITY, lrow0s = 0.f, lrow1s = 0.f;
    float oacc[8][4];
    #pragma unroll
    for (int j = 0; j < 8; j++)
        #pragma unroll
        for (int r = 0; r < 4; r++) oacc[j][r] = 0.f;

    for (int t = 0; t < ntiles; t++) {
        const int s0 = t * 64;
        asm volatile("cp.async.wait_group 0;");
        __syncthreads();
        if (t + 1 < ntiles) loadKV((t + 1) & 1, s0 + 64);

        if (s0 <= my_max) {
            const __half* Kt = Ks + (t & 1) * 64 * AKSTR;
            const __half* Vt = Vs + (t & 1) * 64 * AKSTR;

            float sf[8][4];
            #pragma unroll
            for (int j = 0; j < 8; j++)
                #pragma unroll
                for (int r = 0; r < 4; r++) sf[j][r] = 0.f;
            #pragma unroll
            for (int kc = 0; kc < 4; kc++) {
                #pragma unroll
                for (int jb = 0; jb < 4; jb++) {
                    uint32_t kf[4];
                    ldm_x4(kf, smem_u32(Kt + (jb * 16 + lrow) * AKSTR + kc * 16 + lcol));
                    mma_fp16_2(sf[2*jb],   qf[kc], kf[0], kf[2]);
                    mma_fp16_2(sf[2*jb+1], qf[kc], kf[1], kf[3]);
                }
            }

            if (s0 + 63 > qt0 + m0) {
                #pragma unroll
                for (int j = 0; j < 8; j++) {
                    int c0 = s0 + j * 8 + 2 * tg, c1 = c0 + 1;
                    if (c0 > r0)     sf[j][0] = -INFINITY;
                    if (c1 > r0)     sf[j][1] = -INFINITY;
                    if (c0 > r0 + 8) sf[j][2] = -INFINITY;
                    if (c1 > r0 + 8) sf[j][3] = -INFINITY;
                }
            }

            float mx0 = -INFINITY, mx1 = -INFINITY;
            #pragma unroll
            for (int j = 0; j < 8; j++) {
                mx0 = fmaxf(mx0, fmaxf(sf[j][0], sf[j][1]));
                mx1 = fmaxf(mx1, fmaxf(sf[j][2], sf[j][3]));
            }
            mx0 = fmaxf(mx0, __shfl_xor_sync(0xffffffffu, mx0, 1));
            mx0 = fmaxf(mx0, __shfl_xor_sync(0xffffffffu, mx0, 2));
            mx1 = fmaxf(mx1, __shfl_xor_sync(0xffffffffu, mx1, 1));
            mx1 = fmaxf(mx1, __shfl_xor_sync(0xffffffffu, mx1, 2));

            float mn0 = fmaxf(mrow0, mx0), mn1 = fmaxf(mrow1, mx1);
            float corr0 = exp2f(mrow0 - mn0), corr1 = exp2f(mrow1 - mn1);
            mrow0 = mn0; mrow1 = mn1;

            uint32_t pj[8][2];
            #pragma unroll
            for (int j = 0; j < 8; j++) {
                __half2 e0 = h2exp2(__floats2half2_rn(sf[j][0] - mn0, sf[j][1] - mn0));
                __half2 e1 = h2exp2(__floats2half2_rn(sf[j][2] - mn1, sf[j][3] - mn1));
                pj[j][0] = *reinterpret_cast<uint32_t*>(&e0);
                pj[j][1] = *reinterpret_cast<uint32_t*>(&e1);
            }

            #pragma unroll
            for (int j = 0; j < 8; j++) {
                oacc[j][0] *= corr0; oacc[j][1] *= corr0;
                oacc[j][2] *= corr1; oacc[j][3] *= corr1;
            }

            float lacc[4] = {0.f, 0.f, 0.f, 0.f};
            #pragma unroll
            for (int kk = 0; kk < 4; kk++) {
                uint32_t ap[4] = { pj[2*kk][0], pj[2*kk][1],
                                   pj[2*kk+1][0], pj[2*kk+1][1] };
                mma_fp16_2(lacc, ap, ONE2, ONE2);
                #pragma unroll
                for (int db = 0; db < 4; db++) {
                    uint32_t vf[4];
                    ldm_x4_t(vf, smem_u32(Vt + (kk * 16 + lrow) * AKSTR + db * 16 + lcol));
                    mma_fp16_2(oacc[2*db],   ap, vf[0], vf[1]);
                    mma_fp16_2(oacc[2*db+1], ap, vf[2], vf[3]);
                }
            }
            lrow0s = lrow0s * corr0 + lacc[0];
            lrow1s = lrow1s * corr1 + lacc[2];
        }
    }

    float inv0 = 1.f / lrow0s;
    float inv1 = 1.f / lrow1s;
    __half* ob0 = o + ((size_t)(b * T_ + r0)) * C_ + h * HS_;
    __half* ob1 = ob0 + (size_t)8 * C_;
    #pragma unroll
    for (int j = 0; j < 8; j++) {
        int col = j * 8 + 2 * tg;
        *(__half2*)(ob0 + col) = __floats2half2_rn(oacc[j][0] * inv0, oacc[j][1] * inv0);
        *(__half2*)(ob1 + col) = __floats2half2_rn(oacc[j][2] * inv1, oacc[j][3] * inv1);
    }
}

// ---------------- launch ----------------
extern "C" void kernel_launch(void* const* d_in, const int* in_sizes, int n_in,
                              void* d_out, int out_size)
{
    const float* x     = (const float*)d_in[0];
    const float* Wq    = (const float*)d_in[1];
    const float* Wk    = (const float*)d_in[2];
    const float* Wv    = (const float*)d_in[3];
    const float* Wproj = (const float*)d_in[4];
    const float* bproj = (const float*)d_in[5];
    const float* W1    = (const float*)d_in[6];
    const float* b1    = (const float*)d_in[7];
    const float* W2    = (const float*)d_in[8];
    const float* b2    = (const float*)d_in[9];
    const float* ln1g  = (const float*)d_in[10];
    const float* ln1b  = (const float*)d_in[11];
    const float* ln2g  = (const float*)d_in[12];
    const float* ln2b  = (const float*)d_in[13];
    float* out = (float*)d_out;

    __half *h, *qkv, *ob, *ff, *wqkv, *wp, *w1, *w2;
    float *x1;
    cudaGetSymbolAddress((void**)&h,    g_h);
    cudaGetSymbolAddress((void**)&qkv,  g_qkv);
    cudaGetSymbolAddress((void**)&ob,   g_o);
    cudaGetSymbolAddress((void**)&x1,   g_x1);
    cudaGetSymbolAddress((void**)&ff,   g_ff);
    cudaGetSymbolAddress((void**)&wqkv, g_wqkv);
    cudaGetSymbolAddress((void**)&wp,   g_wp);
    cudaGetSymbolAddress((void**)&w1,   g_w1);
    cudaGetSymbolAddress((void**)&w2,   g_w2);

    cudaFuncSetAttribute(gemm_fp16, cudaFuncAttributeMaxDynamicSharedMemorySize, HG_SMEM);
    cudaFuncSetAttribute(attn_h,    cudaFuncAttributeMaxDynamicSharedMemorySize, ATTN_SMEM);

    dim3 tb(32, 8);

    // 1. LN1 -> half
    ln_kernel<<<M_, 256>>>(x, ln1g, ln1b, h);

    // 2. qkv weight repack
    repack_qkv3T<<<(C3_*C_)/256, 256>>>(Wq, Wk, Wv, wqkv);

    // 3. fused QKV projection -> half
    gemm_fp16<<<dim3(M_/128, C3_/128), 256, HG_SMEM>>>(h, wqkv, qkv, M_, C3_, C_,
                                                       nullptr, nullptr, 0, 2);

    // 4. fp16 causal flash attention -> half g_o   [ncu profile slot]
    dim3 ga(T_/128, H_, B_);
    attn_h<<<ga, 256, ATTN_SMEM>>>(qkv, ob);

    // 5. Wproj transpose
    transpose_h<<<dim3(C_/32,  C_/32),  tb>>>(Wproj, wp, C_,  C_);

    // 6. x1 = x + o @ Wproj + bproj  (fp32 out)
    gemm_fp16<<<dim3(M_/128, C_/128), 256, HG_SMEM>>>(ob, wp, x1, M_, C_, C_,
                                                      bproj, x, 0, 0);

    // 7. LN2 -> half
    ln_kernel<<<M_, 256>>>(x1, ln2g, ln2b, h);

    // 8. W1 transpose
    transpose_h<<<dim3(FF_/32, C_/32),  tb>>>(W1, w1, C_, FF_);

    // 9. ff = relu(h @ W1 + b1) -> half
    gemm_fp16<<<dim3(M_/128, FF_/128), 256, HG_SMEM>>>(h, w1, ff, M_, FF_, C_,
                                                       b1, nullptr, 1, 2);

    // 10. W2 transpose
    transpose_h<<<dim3(C_/32,  FF_/32), tb>>>(W2, w2, FF_, C_);

    // 11. out = x1 + ff @ W2 + b2  (final, fp32 out)
    gemm_fp16<<<dim3(M_/128, C_/128), 256, HG_SMEM>>>(ff, w2, out, M_, C_, FF_,
                                                      b2, x1, 0, 0);
}

// round 14
// speedup vs baseline: 1.0353x; 1.0353x over previous
#include <cuda_runtime.h>
#include <cuda_fp16.h>
#include <math.h>
#include <stdint.h>

// Problem constants
#define B_  4
#define T_  2048
#define C_  1024
#define C3_ 3072
#define H_  16
#define HS_ 64
#define FF_ 4096
#define M_  (B_*T_)     // 8192 rows
#define EPS_ 1e-5f

// ---------------- scratch (no dynamic alloc allowed) ----------------
__device__ __half g_h   [M_*C_];    // LN output (half)
__device__ __half g_qkv [M_*C3_];   // fused q|k|v (half), row stride 3072
__device__ __half g_o   [M_*C_];    // attention output (half)
__device__ float  g_x1  [M_*C_];    // x + attn_out @ Wproj + bproj (fp32)
__device__ __half g_ff  [M_*FF_];   // relu(h2 @ W1 + b1) (half)
__device__ __half g_wqkv[C3_*C_];   // repacked+transposed [3C, C] qkv weight (half)
__device__ __half g_wp  [C_*C_];    // transposed Wproj [N,K] (half)
__device__ __half g_w1  [FF_*C_];   // transposed W1 [4096,1024] (half)
__device__ __half g_w2  [C_*FF_];   // transposed W2 [1024,4096] (half)

__device__ __forceinline__ uint32_t f2tf32(float f) {
    uint32_t u;
    asm("cvt.rna.tf32.f32 %0, %1;" : "=r"(u) : "f"(f));
    return u;
}
__device__ __forceinline__ float roundtf(float f) {
    return __uint_as_float(f2tf32(f));
}

// fp16 mma
__device__ __forceinline__ void mma_fp16(float* c, const uint32_t* a, const uint32_t* b) {
    asm volatile("mma.sync.aligned.m16n8k16.row.col.f32.f16.f16.f32 "
        "{%0,%1,%2,%3}, {%4,%5,%6,%7}, {%8,%9}, {%0,%1,%2,%3};"
        : "+f"(c[0]), "+f"(c[1]), "+f"(c[2]), "+f"(c[3])
        : "r"(a[0]), "r"(a[1]), "r"(a[2]), "r"(a[3]), "r"(b[0]), "r"(b[1]));
}
__device__ __forceinline__ void mma_fp16_2(float* c, const uint32_t* a,
                                           uint32_t b0, uint32_t b1) {
    asm volatile("mma.sync.aligned.m16n8k16.row.col.f32.f16.f16.f32 "
        "{%0,%1,%2,%3}, {%4,%5,%6,%7}, {%8,%9}, {%0,%1,%2,%3};"
        : "+f"(c[0]), "+f"(c[1]), "+f"(c[2]), "+f"(c[3])
        : "r"(a[0]), "r"(a[1]), "r"(a[2]), "r"(a[3]), "r"(b0), "r"(b1));
}
__device__ __forceinline__ void ldm_x4(uint32_t* r, uint32_t addr) {
    asm volatile("ldmatrix.sync.aligned.m8n8.x4.shared.b16 {%0,%1,%2,%3}, [%4];"
        : "=r"(r[0]), "=r"(r[1]), "=r"(r[2]), "=r"(r[3]) : "r"(addr));
}
__device__ __forceinline__ void ldm_x4_t(uint32_t* r, uint32_t addr) {
    asm volatile("ldmatrix.sync.aligned.m8n8.x4.trans.shared.b16 {%0,%1,%2,%3}, [%4];"
        : "=r"(r[0]), "=r"(r[1]), "=r"(r[2]), "=r"(r[3]) : "r"(addr));
}
__device__ __forceinline__ uint32_t smem_u32(const void* p) {
    return (uint32_t)__cvta_generic_to_shared(p);
}

// ---------------- LayerNorm: fp32 in, half out (warp-shuffle reduce) -------------
__global__ __launch_bounds__(256) void ln_kernel(const float* __restrict__ x,
                                                 const float* __restrict__ g,
                                                 const float* __restrict__ b,
                                                 __half* __restrict__ y)
{
    int row = blockIdx.x;
    const float* xr = x + (size_t)row * C_;
    __half* yr = y + (size_t)row * C_;
    int tid = threadIdx.x;
    int wid = tid >> 5, lane = tid & 31;

    float4 v = *(const float4*)(xr + tid * 4);
    float s  = v.x + v.y + v.z + v.w;
    float s2 = v.x * v.x + v.y * v.y + v.z * v.z + v.w * v.w;
    #pragma unroll
    for (int off = 16; off > 0; off >>= 1) {
        s  += __shfl_xor_sync(0xffffffffu, s,  off);
        s2 += __shfl_xor_sync(0xffffffffu, s2, off);
    }
    __shared__ float ws[8], ws2[8];
    if (lane == 0) { ws[wid] = s; ws2[wid] = s2; }
    __syncthreads();
    if (wid == 0) {
        float a  = (lane < 8) ? ws[lane]  : 0.f;
        float a2 = (lane < 8) ? ws2[lane] : 0.f;
        #pragma unroll
        for (int off = 4; off > 0; off >>= 1) {
            a  += __shfl_xor_sync(0xffffffffu, a,  off);
            a2 += __shfl_xor_sync(0xffffffffu, a2, off);
        }
        if (lane == 0) { ws[0] = a; ws2[0] = a2; }
    }
    __syncthreads();
    float mean = ws[0] * (1.0f / C_);
    float var  = ws2[0] * (1.0f / C_) - mean * mean;
    float rstd = rsqrtf(var + EPS_);

    const float4 gv = *(const float4*)(g + tid * 4);
    const float4 bv = *(const float4*)(b + tid * 4);
    __half2 h0 = __floats2half2_rn((v.x - mean) * rstd * gv.x + bv.x,
                                   (v.y - mean) * rstd * gv.y + bv.y);
    __half2 h1 = __floats2half2_rn((v.z - mean) * rstd * gv.z + bv.z,
                                   (v.w - mean) * rstd * gv.w + bv.w);
    *(__half2*)(yr + tid * 4)     = h0;
    *(__half2*)(yr + tid * 4 + 2) = h1;
}

// ---------------- repack [H,C,HS]x3 -> [3C, C] half ----------------
__global__ void repack_qkv3T(const float* __restrict__ Wq,
                             const float* __restrict__ Wk,
                             const float* __restrict__ Wv,
                             __half* __restrict__ Wt)
{
    int idx = blockIdx.x * 256 + threadIdx.x;   // idx = n*C + c
    if (idx < C3_*C_) {
        int n = idx >> 10;
        int c = idx & (C_ - 1);
        int sec = n >> 10;
        int nn = n & (C_ - 1);
        int h = nn >> 6;
        int d = nn & (HS_ - 1);
        const float* W = (sec == 0) ? Wq : (sec == 1) ? Wk : Wv;
        Wt[idx] = __float2half_rn(W[(size_t)h * C_ * HS_ + (size_t)c * HS_ + d]);
    }
}

// ---------------- transpose to half: src [R, Cc] fp32 -> dst [Cc, R] half -------
__global__ void transpose_h(const float* __restrict__ S, __half* __restrict__ D,
                            int R, int Cc)
{
    __shared__ float t[32][33];
    int bx = blockIdx.x * 32, by = blockIdx.y * 32;
    int x = threadIdx.x, y = threadIdx.y;
    #pragma unroll
    for (int i = 0; i < 32; i += 8)
        t[y + i][x] = S[(size_t)(by + y + i) * Cc + bx + x];
    __syncthreads();
    #pragma unroll
    for (int i = 0; i < 32; i += 8)
        D[(size_t)(bx + y + i) * R + by + x] = __float2half_rn(t[x][y + i]);
}

// ---------------- fp16 mma.sync GEMM, BK=64, 2-stage (R12 config) ----------------
// C[M,N] = A[M,K] @ Bt[N,K]^T  (+bias)(+res)(relu)
// out_mode: 0 = fp32, 1 = fp32 tf32-rounded, 2 = half
// 128x128 CTA tile, BK=64 halves, 8 warps at 64x32, 2 CTA/SM (2x73.7KB smem).
#define HSTR 72
#define HG_STAGE (2*128*HSTR)          // halves per stage (A+B) = 18432
#define HG_SMEM  (2*HG_STAGE*2)        // 73728 bytes

__global__ __launch_bounds__(256, 2) void gemm_fp16(const __half* __restrict__ A,
                                                    const __half* __restrict__ Bt,
                                                    void* __restrict__ Cm,
                                                    int Mn, int Nn, int Kn,
                                                    const float* __restrict__ bias,
                                                    const float* __restrict__ res,
                                                    int relu, int out_mode)
{
    extern __shared__ __half smh[];
    const int tid = threadIdx.x;
    const int wid = tid >> 5, lane = tid & 31;
    const int g = lane >> 2, tg = lane & 3;
    const int warp_m = wid >> 2;       // 0..1  (64 rows)
    const int warp_n = wid & 3;        // 0..3  (32 cols)
    const int bm = blockIdx.x * 128;
    const int bn = blockIdx.y * 128;

    const int a_row  = lane & 15;
    const int a_koff = (lane >> 4) << 3;
    const int b_row  = ((lane >> 4) << 3) + (lane & 7);
    const int b_koff = ((lane >> 3) & 1) << 3;

    float acc[4][4][4];
    #pragma unroll
    for (int mi = 0; mi < 4; mi++)
        #pragma unroll
        for (int ni = 0; ni < 4; ni++)
            #pragma unroll
            for (int r = 0; r < 4; r++) acc[mi][ni][r] = 0.f;

    auto fill = [&](int s, int kt) {
        const int k0 = kt << 6;
        __half* As = smh + s * HG_STAGE;
        __half* Bs = As + 128 * HSTR;
        #pragma unroll
        for (int i = 0; i < 4; i++) {
            int idx = tid + (i << 8);          // 1024 chunks of 16B per matrix
            int r = idx >> 3, c8 = (idx & 7) << 3;
            uint32_t da = smem_u32(As + r * HSTR + c8);
            asm volatile("cp.async.cg.shared.global [%0], [%1], 16;"
                         :: "r"(da), "l"(A + (size_t)(bm + r) * Kn + k0 + c8));
            uint32_t db = smem_u32(Bs + r * HSTR + c8);
            asm volatile("cp.async.cg.shared.global [%0], [%1], 16;"
                         :: "r"(db), "l"(Bt + (size_t)(bn + r) * Kn + k0 + c8));
        }
        asm volatile("cp.async.commit_group;");
    };

    const int KT = Kn >> 6;
    fill(0, 0);

    for (int kt = 0; kt < KT; kt++) {
        asm volatile("cp.async.wait_group 0;");
        __syncthreads();
        if (kt + 1 < KT) fill((kt + 1) & 1, kt + 1);

        const __half* As = smh + (kt & 1) * HG_STAGE;
        const __half* Bs = As + 128 * HSTR;

        #pragma unroll
        for (int ks = 0; ks < 4; ks++) {
            const int kb0 = ks * 16;
            uint32_t af[4][4], bq[2][4];
            #pragma unroll
            for (int mi = 0; mi < 4; mi++)
                ldm_x4(af[mi], smem_u32(As + (warp_m * 64 + mi * 16 + a_row) * HSTR
                                           + kb0 + a_koff));
            #pragma unroll
            for (int np = 0; np < 2; np++)
                ldm_x4(bq[np], smem_u32(Bs + (warp_n * 32 + np * 16 + b_row) * HSTR
                                           + kb0 + b_koff));
            #pragma unroll
            for (int mi = 0; mi < 4; mi++)
                #pragma unroll
                for (int ni = 0; ni < 4; ni++)
                    mma_fp16(acc[mi][ni], af[mi], &bq[ni >> 1][(ni & 1) * 2]);
        }
        // no trailing sync: next iteration's top __syncthreads orders
        // this compute before fill overwrites the other stage.
    }

    #pragma unroll
    for (int mi = 0; mi < 4; mi++) {
        #pragma unroll
        for (int ni = 0; ni < 4; ni++) {
            int row0 = bm + warp_m * 64 + mi * 16 + g;
            int col  = bn + warp_n * 32 + ni * 8 + tg * 2;
            float bx = 0.f, by = 0.f;
            if (bias) { bx = bias[col]; by = bias[col + 1]; }
            #pragma unroll
            for (int half_ = 0; half_ < 2; half_++) {
                int row = row0 + half_ * 8;
                float v0 = acc[mi][ni][half_ * 2 + 0] + bx;
                float v1 = acc[mi][ni][half_ * 2 + 1] + by;
                if (res) {
                    const float* rp = res + (size_t)row * Nn + col;
                    v0 += rp[0]; v1 += rp[1];
                }
                if (relu) { v0 = fmaxf(v0, 0.f); v1 = fmaxf(v1, 0.f); }
                if (out_mode == 2) {
                    __half2 hv = __floats2half2_rn(v0, v1);
                    *(__half2*)((__half*)Cm + (size_t)row * Nn + col) = hv;
                } else {
                    if (out_mode == 1) { v0 = roundtf(v0); v1 = roundtf(v1); }
                    *(float2*)((float*)Cm + (size_t)row * Nn + col) = make_float2(v0, v1);
                }
            }
        }
    }
}

// ---------------- fp16 tensor-core flash attention (R12, unchanged) -------------
#define AKSTR 72
#define AQSTR 72
#define ATTN_SMEM ((4*64*AKSTR + 128*AQSTR)*2)   // 55296 bytes

__global__ __launch_bounds__(256, 2) void attn_h(const __half* __restrict__ qkv,
                                                 __half* __restrict__ o)
{
    extern __shared__ __half smha[];
    __half* Ks = smha;                    // 2 stages 64 x AKSTR
    __half* Vs = smha + 2*64*AKSTR;       // 2 stages 64 x AKSTR
    __half* Qs = Vs + 2*64*AKSTR;         // 128 x AQSTR (Q, pre-scaled)

    const int tid = threadIdx.x, wid = tid >> 5, lane = tid & 31;
    const int g = lane >> 2, tg = lane & 3;
    const int qt0 = blockIdx.x * 128;
    const int h = blockIdx.y, b = blockIdx.z;

    const __half* qbase = qkv + (size_t)(b * T_ + qt0) * C3_ + h * HS_;
    const __half* kbase = qkv + (size_t)b * T_ * C3_ + C_  + h * HS_;
    const __half* vbase = qkv + (size_t)b * T_ * C3_ + 2*C_ + h * HS_;

    // stage Q tile (128x64 half), pre-scaled by log2(e)/8
    {
        int r = tid >> 1, c = (tid & 1) * 32;
        const __half2 s8 = __float2half2_rn(0.1803368801f);   // log2(e)/8
        #pragma unroll
        for (int i = 0; i < 4; i++) {
            __half2 v[4];
            *(uint4*)v = *(const uint4*)(qbase + (size_t)r * C3_ + c + i * 8);
            #pragma unroll
            for (int j = 0; j < 4; j++) v[j] = __hmul2(v[j], s8);
            *(uint4*)(Qs + r * AQSTR + c + i * 8) = *(uint4*)v;
        }
    }

    const int m0 = wid * 16;
    const int r0 = qt0 + m0 + g;
    const int my_max = qt0 + m0 + 15;
    const int ntiles = (qt0 + 128) >> 6;
    const int lrow = lane & 15;
    const int lcol = (lane >> 4) << 3;
    const uint32_t ONE2 = 0x3C003C00u;    // half2(1, 1)

    auto loadKV = [&](int s, int s0) {
        const __half* kp = kbase + (size_t)s0 * C3_;
        const __half* vp = vbase + (size_t)s0 * C3_;
        __half* Kd = Ks + s * 64 * AKSTR;
        __half* Vd = Vs + s * 64 * AKSTR;
        #pragma unroll
        for (int i = 0; i < 2; i++) {
            int idx = tid + (i << 8);           // 512 chunks of 16B per matrix
            int r = idx >> 3, c8 = (idx & 7) * 8;
            uint32_t dk = smem_u32(Kd + r * AKSTR + c8);
            asm volatile("cp.async.cg.shared.global [%0], [%1], 16;"
                         :: "r"(dk), "l"(kp + (size_t)r * C3_ + c8));
            uint32_t dv = smem_u32(Vd + r * AKSTR + c8);
            asm volatile("cp.async.cg.shared.global [%0], [%1], 16;"
                         :: "r"(dv), "l"(vp + (size_t)r * C3_ + c8));
        }
        asm volatile("cp.async.commit_group;");
    };

    loadKV(0, 0);
    __syncthreads();      // Q staging visible

    uint32_t qf[4][4];
    #pragma unroll
    for (int kc = 0; kc < 4; kc++)
        ldm_x4(qf[kc], smem_u32(Qs + (m0 + lrow) * AQSTR + kc * 16 + lcol));

    float mrow0 = -INFINITY, mrow1 = -INFINITY, lrow0s = 0.f, lrow1s = 0.f;
    float oacc[8][4];
    #pragma unroll
    for (int j = 0; j < 8; j++)
        #pragma unroll
        for (int r = 0; r < 4; r++) oacc[j][r] = 0.f;

    for (int t = 0; t < ntiles; t++) {
        const int s0 = t * 64;
        asm volatile("cp.async.wait_group 0;");
        __syncthreads();
        if (t + 1 < ntiles) loadKV((t + 1) & 1, s0 + 64);

        if (s0 <= my_max) {
            const __half* Kt = Ks + (t & 1) * 64 * AKSTR;
            const __half* Vt = Vs + (t & 1) * 64 * AKSTR;

            float sf[8][4];
            #pragma unroll
            for (int j = 0; j < 8; j++)
                #pragma unroll
                for (int r = 0; r < 4; r++) sf[j][r] = 0.f;
            #pragma unroll
            for (int kc = 0; kc < 4; kc++) {
                #pragma unroll
                for (int jb = 0; jb < 4; jb++) {
                    uint32_t kf[4];
                    ldm_x4(kf, smem_u32(Kt + (jb * 16 + lrow) * AKSTR + kc * 16 + lcol));
                    mma_fp16_2(sf[2*jb],   qf[kc], kf[0], kf[2]);
                    mma_fp16_2(sf[2*jb+1], qf[kc], kf[1], kf[3]);
                }
            }

            if (s0 + 63 > qt0 + m0) {
                #pragma unroll
                for (int j = 0; j < 8; j++) {
                    int c0 = s0 + j * 8 + 2 * tg, c1 = c0 + 1;
                    if (c0 > r0)     sf[j][0] = -INFINITY;
                    if (c1 > r0)     sf[j][1] = -INFINITY;
                    if (c0 > r0 + 8) sf[j][2] = -INFINITY;
                    if (c1 > r0 + 8) sf[j][3] = -INFINITY;
                }
            }

            float mx0 = -INFINITY, mx1 = -INFINITY;
            #pragma unroll
            for (int j = 0; j < 8; j++) {
                mx0 = fmaxf(mx0, fmaxf(sf[j][0], sf[j][1]));
                mx1 = fmaxf(mx1, fmaxf(sf[j][2], sf[j][3]));
            }
            mx0 = fmaxf(mx0, __shfl_xor_sync(0xffffffffu, mx0, 1));
            mx0 = fmaxf(mx0, __shfl_xor_sync(0xffffffffu, mx0, 2));
            mx1 = fmaxf(mx1, __shfl_xor_sync(0xffffffffu, mx1, 1));
            mx1 = fmaxf(mx1, __shfl_xor_sync(0xffffffffu, mx1, 2));

            float mn0 = fmaxf(mrow0, mx0), mn1 = fmaxf(mrow1, mx1);
            float corr0 = exp2f(mrow0 - mn0), corr1 = exp2f(mrow1 - mn1);
            mrow0 = mn0; mrow1 = mn1;

            uint32_t pj[8][2];
            #pragma unroll
            for (int j = 0; j < 8; j++) {
                __half2 e0 = h2exp2(__floats2half2_rn(sf[j][0] - mn0, sf[j][1] - mn0));
                __half2 e1 = h2exp2(__floats2half2_rn(sf[j][2] - mn1, sf[j][3] - mn1));
                pj[j][0] = *reinterpret_cast<uint32_t*>(&e0);
                pj[j][1] = *reinterpret_cast<uint32_t*>(&e1);
            }

            #pragma unroll
            for (int j = 0; j < 8; j++) {
                oacc[j][0] *= corr0; oacc[j][1] *= corr0;
                oacc[j][2] *= corr1; oacc[j][3] *= corr1;
            }

            float lacc[4] = {0.f, 0.f, 0.f, 0.f};
            #pragma unroll
            for (int kk = 0; kk < 4; kk++) {
                uint32_t ap[4] = { pj[2*kk][0], pj[2*kk][1],
                                   pj[2*kk+1][0], pj[2*kk+1][1] };
                mma_fp16_2(lacc, ap, ONE2, ONE2);
                #pragma unroll
                for (int db = 0; db < 4; db++) {
                    uint32_t vf[4];
                    ldm_x4_t(vf, smem_u32(Vt + (kk * 16 + lrow) * AKSTR + db * 16 + lcol));
                    mma_fp16_2(oacc[2*db],   ap, vf[0], vf[1]);
                    mma_fp16_2(oacc[2*db+1], ap, vf[2], vf[3]);
                }
            }
            lrow0s = lrow0s * corr0 + lacc[0];
            lrow1s = lrow1s * corr1 + lacc[2];
        }
    }

    float inv0 = 1.f / lrow0s;
    float inv1 = 1.f / lrow1s;
    __half* ob0 = o + ((size_t)(b * T_ + r0)) * C_ + h * HS_;
    __half* ob1 = ob0 + (size_t)8 * C_;
    #pragma unroll
    for (int j = 0; j < 8; j++) {
        int col = j * 8 + 2 * tg;
        *(__half2*)(ob0 + col) = __floats2half2_rn(oacc[j][0] * inv0, oacc[j][1] * inv0);
        *(__half2*)(ob1 + col) = __floats2half2_rn(oacc[j][2] * inv1, oacc[j][3] * inv1);
    }
}

// ---------------- launch ----------------
extern "C" void kernel_launch(void* const* d_in, const int* in_sizes, int n_in,
                              void* d_out, int out_size)
{
    const float* x     = (const float*)d_in[0];
    const float* Wq    = (const float*)d_in[1];
    const float* Wk    = (const float*)d_in[2];
    const float* Wv    = (const float*)d_in[3];
    const float* Wproj = (const float*)d_in[4];
    const float* bproj = (const float*)d_in[5];
    const float* W1    = (const float*)d_in[6];
    const float* b1    = (const float*)d_in[7];
    const float* W2    = (const float*)d_in[8];
    const float* b2    = (const float*)d_in[9];
    const float* ln1g  = (const float*)d_in[10];
    const float* ln1b  = (const float*)d_in[11];
    const float* ln2g  = (const float*)d_in[12];
    const float* ln2b  = (const float*)d_in[13];
    float* out = (float*)d_out;

    __half *h, *qkv, *ob, *ff, *wqkv, *wp, *w1, *w2;
    float *x1;
    cudaGetSymbolAddress((void**)&h,    g_h);
    cudaGetSymbolAddress((void**)&qkv,  g_qkv);
    cudaGetSymbolAddress((void**)&ob,   g_o);
    cudaGetSymbolAddress((void**)&x1,   g_x1);
    cudaGetSymbolAddress((void**)&ff,   g_ff);
    cudaGetSymbolAddress((void**)&wqkv, g_wqkv);
    cudaGetSymbolAddress((void**)&wp,   g_wp);
    cudaGetSymbolAddress((void**)&w1,   g_w1);
    cudaGetSymbolAddress((void**)&w2,   g_w2);

    cudaFuncSetAttribute(gemm_fp16, cudaFuncAttributeMaxDynamicSharedMemorySize, HG_SMEM);
    cudaFuncSetAttribute(attn_h,    cudaFuncAttributeMaxDynamicSharedMemorySize, ATTN_SMEM);

    dim3 tb(32, 8);

    // 1. LN1 -> half
    ln_kernel<<<M_, 256>>>(x, ln1g, ln1b, h);

    // 2. qkv weight repack
    repack_qkv3T<<<(C3_*C_)/256, 256>>>(Wq, Wk, Wv, wqkv);

    // 3. fused QKV projection -> half
    gemm_fp16<<<dim3(M_/128, C3_/128), 256, HG_SMEM>>>(h, wqkv, qkv, M_, C3_, C_,
                                                       nullptr, nullptr, 0, 2);

    // 4. fp16 causal flash attention -> half g_o   [ncu profile slot]
    dim3 ga(T_/128, H_, B_);
    attn_h<<<ga, 256, ATTN_SMEM>>>(qkv, ob);

    // 5. Wproj transpose
    transpose_h<<<dim3(C_/32,  C_/32),  tb>>>(Wproj, wp, C_,  C_);

    // 6. x1 = x + o @ Wproj + bproj  (fp32 out)
    gemm_fp16<<<dim3(M_/128, C_/128), 256, HG_SMEM>>>(ob, wp, x1, M_, C_, C_,
                                                      bproj, x, 0, 0);

    // 7. LN2 -> half
    ln_kernel<<<M_, 256>>>(x1, ln2g, ln2b, h);

    // 8. W1 transpose
    transpose_h<<<dim3(FF_/32, C_/32),  tb>>>(W1, w1, C_, FF_);

    // 9. ff = relu(h @ W1 + b1) -> half
    gemm_fp16<<<dim3(M_/128, FF_/128), 256, HG_SMEM>>>(h, w1, ff, M_, FF_, C_,
                                                       b1, nullptr, 1, 2);

    // 10. W2 transpose
    transpose_h<<<dim3(C_/32,  FF_/32), tb>>>(W2, w2, FF_, C_);

    // 11. out = x1 + ff @ W2 + b2  (final, fp32 out)
    gemm_fp16<<<dim3(M_/128, C_/128), 256, HG_SMEM>>>(ff, w2, out, M_, C_, FF_,
                                                      b2, x1, 0, 0);
}

// round 16
// speedup vs baseline: 1.0405x; 1.0050x over previous
#include <cuda_runtime.h>
#include <cuda_fp16.h>
#include <math.h>
#include <stdint.h>

// Problem constants
#define B_  4
#define T_  2048
#define C_  1024
#define C3_ 3072
#define H_  16
#define HS_ 64
#define FF_ 4096
#define M_  (B_*T_)     // 8192 rows
#define EPS_ 1e-5f

// ---------------- scratch (no dynamic alloc allowed) ----------------
__device__ __half g_h   [M_*C_];    // LN output (half)
__device__ __half g_qkv [M_*C3_];   // fused q|k|v (half), row stride 3072
__device__ __half g_o   [M_*C_];    // attention output (half)
__device__ float  g_x1  [M_*C_];    // x + attn_out @ Wproj + bproj (fp32)
__device__ __half g_ff  [M_*FF_];   // relu(h2 @ W1 + b1) (half)
__device__ __half g_wqkv[C3_*C_];   // repacked+transposed [3C, C] qkv weight (half)
__device__ __half g_wp  [C_*C_];    // transposed Wproj [N,K] (half)
__device__ __half g_w1  [FF_*C_];   // transposed W1 [4096,1024] (half)
__device__ __half g_w2  [C_*FF_];   // transposed W2 [1024,4096] (half)

__device__ __forceinline__ uint32_t f2tf32(float f) {
    uint32_t u;
    asm("cvt.rna.tf32.f32 %0, %1;" : "=r"(u) : "f"(f));
    return u;
}
__device__ __forceinline__ float roundtf(float f) {
    return __uint_as_float(f2tf32(f));
}

// fp16 mma
__device__ __forceinline__ void mma_fp16(float* c, const uint32_t* a, const uint32_t* b) {
    asm volatile("mma.sync.aligned.m16n8k16.row.col.f32.f16.f16.f32 "
        "{%0,%1,%2,%3}, {%4,%5,%6,%7}, {%8,%9}, {%0,%1,%2,%3};"
        : "+f"(c[0]), "+f"(c[1]), "+f"(c[2]), "+f"(c[3])
        : "r"(a[0]), "r"(a[1]), "r"(a[2]), "r"(a[3]), "r"(b[0]), "r"(b[1]));
}
__device__ __forceinline__ void mma_fp16_2(float* c, const uint32_t* a,
                                           uint32_t b0, uint32_t b1) {
    asm volatile("mma.sync.aligned.m16n8k16.row.col.f32.f16.f16.f32 "
        "{%0,%1,%2,%3}, {%4,%5,%6,%7}, {%8,%9}, {%0,%1,%2,%3};"
        : "+f"(c[0]), "+f"(c[1]), "+f"(c[2]), "+f"(c[3])
        : "r"(a[0]), "r"(a[1]), "r"(a[2]), "r"(a[3]), "r"(b0), "r"(b1));
}
__device__ __forceinline__ void ldm_x4(uint32_t* r, uint32_t addr) {
    asm volatile("ldmatrix.sync.aligned.m8n8.x4.shared.b16 {%0,%1,%2,%3}, [%4];"
        : "=r"(r[0]), "=r"(r[1]), "=r"(r[2]), "=r"(r[3]) : "r"(addr));
}
__device__ __forceinline__ void ldm_x4_t(uint32_t* r, uint32_t addr) {
    asm volatile("ldmatrix.sync.aligned.m8n8.x4.trans.shared.b16 {%0,%1,%2,%3}, [%4];"
        : "=r"(r[0]), "=r"(r[1]), "=r"(r[2]), "=r"(r[3]) : "r"(addr));
}
__device__ __forceinline__ uint32_t smem_u32(const void* p) {
    return (uint32_t)__cvta_generic_to_shared(p);
}

// ---------------- fused prep mega-kernel ----------------
// One launch containing all mutually-independent prep work:
//   [0, 8192)              LN1 rows (x -> g_h, half)
//   [8192, 8192+12288)     qkv repack blocks ([H,C,HS]x3 -> [3C,C] half)
//   next 1024              Wproj transpose (32x32 tiles)
//   next 4096              W1 transpose
//   next 4096              W2 transpose
#define PREP_LN   8192
#define PREP_RP   12288
#define PREP_TP   1024
#define PREP_T1   4096
#define PREP_T2   4096
#define PREP_GRID (PREP_LN + PREP_RP + PREP_TP + PREP_T1 + PREP_T2)

__device__ __forceinline__ void do_ln_row(const float* __restrict__ xr,
                                          const float* __restrict__ g,
                                          const float* __restrict__ b,
                                          __half* __restrict__ yr,
                                          float* ws, float* ws2)
{
    int tid = threadIdx.x;
    int wid = tid >> 5, lane = tid & 31;

    float4 v = *(const float4*)(xr + tid * 4);
    float s  = v.x + v.y + v.z + v.w;
    float s2 = v.x * v.x + v.y * v.y + v.z * v.z + v.w * v.w;
    #pragma unroll
    for (int off = 16; off > 0; off >>= 1) {
        s  += __shfl_xor_sync(0xffffffffu, s,  off);
        s2 += __shfl_xor_sync(0xffffffffu, s2, off);
    }
    if (lane == 0) { ws[wid] = s; ws2[wid] = s2; }
    __syncthreads();
    if (wid == 0) {
        float a  = (lane < 8) ? ws[lane]  : 0.f;
        float a2 = (lane < 8) ? ws2[lane] : 0.f;
        #pragma unroll
        for (int off = 4; off > 0; off >>= 1) {
            a  += __shfl_xor_sync(0xffffffffu, a,  off);
            a2 += __shfl_xor_sync(0xffffffffu, a2, off);
        }
        if (lane == 0) { ws[0] = a; ws2[0] = a2; }
    }
    __syncthreads();
    float mean = ws[0] * (1.0f / C_);
    float var  = ws2[0] * (1.0f / C_) - mean * mean;
    float rstd = rsqrtf(var + EPS_);

    const float4 gv = *(const float4*)(g + tid * 4);
    const float4 bv = *(const float4*)(b + tid * 4);
    __half2 h0 = __floats2half2_rn((v.x - mean) * rstd * gv.x + bv.x,
                                   (v.y - mean) * rstd * gv.y + bv.y);
    __half2 h1 = __floats2half2_rn((v.z - mean) * rstd * gv.z + bv.z,
                                   (v.w - mean) * rstd * gv.w + bv.w);
    *(__half2*)(yr + tid * 4)     = h0;
    *(__half2*)(yr + tid * 4 + 2) = h1;
}

__device__ __forceinline__ void do_transpose32(const float* __restrict__ S,
                                               __half* __restrict__ D,
                                               int R, int Cc, int bx, int by,
                                               float* t /* 32x33 */)
{
    int tid = threadIdx.x;
    int x = tid & 31, y = tid >> 5;   // y in 0..7
    #pragma unroll
    for (int i = 0; i < 32; i += 8)
        t[(y + i) * 33 + x] = S[(size_t)(by * 32 + y + i) * Cc + bx * 32 + x];
    __syncthreads();
    #pragma unroll
    for (int i = 0; i < 32; i += 8)
        D[(size_t)(bx * 32 + y + i) * R + by * 32 + x] =
            __float2half_rn(t[x * 33 + (y + i)]);
}

__global__ __launch_bounds__(256) void prep_kernel(
    const float* __restrict__ x,
    const float* __restrict__ ln1g, const float* __restrict__ ln1b,
    __half* __restrict__ h,
    const float* __restrict__ Wq, const float* __restrict__ Wk,
    const float* __restrict__ Wv, __half* __restrict__ wqkv,
    const float* __restrict__ Wproj, __half* __restrict__ wp,
    const float* __restrict__ W1, __half* __restrict__ w1,
    const float* __restrict__ W2, __half* __restrict__ w2)
{
    __shared__ float tbuf[32 * 33];      // transpose staging (also covers LN's 16 floats)
    int bidx = blockIdx.x;

    if (bidx < PREP_LN) {
        // LN1 row
        do_ln_row(x + (size_t)bidx * C_, ln1g, ln1b, h + (size_t)bidx * C_,
                  tbuf, tbuf + 8);
        return;
    }
    bidx -= PREP_LN;
    if (bidx < PREP_RP) {
        int idx = bidx * 256 + threadIdx.x;   // idx = n*C + c
        int n = idx >> 10;
        int c = idx & (C_ - 1);
        int sec = n >> 10;
        int nn = n & (C_ - 1);
        int hh = nn >> 6;
        int d = nn & (HS_ - 1);
        const float* W = (sec == 0) ? Wq : (sec == 1) ? Wk : Wv;
        wqkv[idx] = __float2half_rn(W[(size_t)hh * C_ * HS_ + (size_t)c * HS_ + d]);
        return;
    }
    bidx -= PREP_RP;
    if (bidx < PREP_TP) {
        // Wproj: [1024,1024] -> wp [1024,1024]; grid 32x32
        do_transpose32(Wproj, wp, C_, C_, bidx & 31, bidx >> 5, tbuf);
        return;
    }
    bidx -= PREP_TP;
    if (bidx < PREP_T1) {
        // W1: [1024,4096] -> w1 [4096,1024]; bx over 128 (cols), by over 32
        do_transpose32(W1, w1, C_, FF_, bidx & 127, bidx >> 7, tbuf);
        return;
    }
    bidx -= PREP_T1;
    {
        // W2: [4096,1024] -> w2 [1024,4096]; bx over 32 (cols), by over 128
        do_transpose32(W2, w2, FF_, C_, bidx & 31, bidx >> 5, tbuf);
    }
}

// ---------------- LayerNorm (standalone, for LN2) ----------------
__global__ __launch_bounds__(256) void ln_kernel(const float* __restrict__ x,
                                                 const float* __restrict__ g,
                                                 const float* __restrict__ b,
                                                 __half* __restrict__ y)
{
    __shared__ float ws[8], ws2[8];
    int row = blockIdx.x;
    do_ln_row(x + (size_t)row * C_, g, b, y + (size_t)row * C_, ws, ws2);
}

// ---------------- fp16 mma.sync GEMM, BK=64, 2-stage (R12 config) ----------------
// C[M,N] = A[M,K] @ Bt[N,K]^T  (+bias)(+res)(relu)
// out_mode: 0 = fp32, 1 = fp32 tf32-rounded, 2 = half
// 128x128 CTA tile, BK=64 halves, 8 warps at 64x32, 2 CTA/SM (2x73.7KB smem).
#define HSTR 72
#define HG_STAGE (2*128*HSTR)          // halves per stage (A+B) = 18432
#define HG_SMEM  (2*HG_STAGE*2)        // 73728 bytes

__global__ __launch_bounds__(256, 2) void gemm_fp16(const __half* __restrict__ A,
                                                    const __half* __restrict__ Bt,
                                                    void* __restrict__ Cm,
                                                    int Mn, int Nn, int Kn,
                                                    const float* __restrict__ bias,
                                                    const float* __restrict__ res,
                                                    int relu, int out_mode)
{
    extern __shared__ __half smh[];
    const int tid = threadIdx.x;
    const int wid = tid >> 5, lane = tid & 31;
    const int g = lane >> 2, tg = lane & 3;
    const int warp_m = wid >> 2;       // 0..1  (64 rows)
    const int warp_n = wid & 3;        // 0..3  (32 cols)
    const int bm = blockIdx.x * 128;
    const int bn = blockIdx.y * 128;

    const int a_row  = lane & 15;
    const int a_koff = (lane >> 4) << 3;
    const int b_row  = ((lane >> 4) << 3) + (lane & 7);
    const int b_koff = ((lane >> 3) & 1) << 3;

    float acc[4][4][4];
    #pragma unroll
    for (int mi = 0; mi < 4; mi++)
        #pragma unroll
        for (int ni = 0; ni < 4; ni++)
            #pragma unroll
            for (int r = 0; r < 4; r++) acc[mi][ni][r] = 0.f;

    auto fill = [&](int s, int kt) {
        const int k0 = kt << 6;
        __half* As = smh + s * HG_STAGE;
        __half* Bs = As + 128 * HSTR;
        #pragma unroll
        for (int i = 0; i < 4; i++) {
            int idx = tid + (i << 8);          // 1024 chunks of 16B per matrix
            int r = idx >> 3, c8 = (idx & 7) << 3;
            uint32_t da = smem_u32(As + r * HSTR + c8);
            asm volatile("cp.async.cg.shared.global [%0], [%1], 16;"
                         :: "r"(da), "l"(A + (size_t)(bm + r) * Kn + k0 + c8));
            uint32_t db = smem_u32(Bs + r * HSTR + c8);
            asm volatile("cp.async.cg.shared.global [%0], [%1], 16;"
                         :: "r"(db), "l"(Bt + (size_t)(bn + r) * Kn + k0 + c8));
        }
        asm volatile("cp.async.commit_group;");
    };

    const int KT = Kn >> 6;
    fill(0, 0);

    for (int kt = 0; kt < KT; kt++) {
        asm volatile("cp.async.wait_group 0;");
        __syncthreads();
        if (kt + 1 < KT) fill((kt + 1) & 1, kt + 1);

        const __half* As = smh + (kt & 1) * HG_STAGE;
        const __half* Bs = As + 128 * HSTR;

        #pragma unroll
        for (int ks = 0; ks < 4; ks++) {
            const int kb0 = ks * 16;
            uint32_t af[4][4], bq[2][4];
            #pragma unroll
            for (int mi = 0; mi < 4; mi++)
                ldm_x4(af[mi], smem_u32(As + (warp_m * 64 + mi * 16 + a_row) * HSTR
                                           + kb0 + a_koff));
            #pragma unroll
            for (int np = 0; np < 2; np++)
                ldm_x4(bq[np], smem_u32(Bs + (warp_n * 32 + np * 16 + b_row) * HSTR
                                           + kb0 + b_koff));
            #pragma unroll
            for (int mi = 0; mi < 4; mi++)
                #pragma unroll
                for (int ni = 0; ni < 4; ni++)
                    mma_fp16(acc[mi][ni], af[mi], &bq[ni >> 1][(ni & 1) * 2]);
        }
        // no trailing sync: next iteration's top __syncthreads orders
        // this compute before fill overwrites the other stage.
    }

    #pragma unroll
    for (int mi = 0; mi < 4; mi++) {
        #pragma unroll
        for (int ni = 0; ni < 4; ni++) {
            int row0 = bm + warp_m * 64 + mi * 16 + g;
            int col  = bn + warp_n * 32 + ni * 8 + tg * 2;
            float bx = 0.f, by = 0.f;
            if (bias) { bx = bias[col]; by = bias[col + 1]; }
            #pragma unroll
            for (int half_ = 0; half_ < 2; half_++) {
                int row = row0 + half_ * 8;
                float v0 = acc[mi][ni][half_ * 2 + 0] + bx;
                float v1 = acc[mi][ni][half_ * 2 + 1] + by;
                if (res) {
                    const float* rp = res + (size_t)row * Nn + col;
                    v0 += rp[0]; v1 += rp[1];
                }
                if (relu) { v0 = fmaxf(v0, 0.f); v1 = fmaxf(v1, 0.f); }
                if (out_mode == 2) {
                    __half2 hv = __floats2half2_rn(v0, v1);
                    *(__half2*)((__half*)Cm + (size_t)row * Nn + col) = hv;
                } else {
                    if (out_mode == 1) { v0 = roundtf(v0); v1 = roundtf(v1); }
                    *(float2*)((float*)Cm + (size_t)row * Nn + col) = make_float2(v0, v1);
                }
            }
        }
    }
}

// ---------------- fp16 tensor-core flash attention ----------------
// Heavy-first CTA order: qt0 decreases with blockIdx.x so the 16-tile CTAs
// launch in the first wave (longest-job-first tail packing).
#define AKSTR 72
#define AQSTR 72
#define ATTN_SMEM ((4*64*AKSTR + 128*AQSTR)*2)   // 55296 bytes

__global__ __launch_bounds__(256, 2) void attn_h(const __half* __restrict__ qkv,
                                                 __half* __restrict__ o)
{
    extern __shared__ __half smha[];
    __half* Ks = smha;                    // 2 stages 64 x AKSTR
    __half* Vs = smha + 2*64*AKSTR;       // 2 stages 64 x AKSTR
    __half* Qs = Vs + 2*64*AKSTR;         // 128 x AQSTR (Q, pre-scaled)

    const int tid = threadIdx.x, wid = tid >> 5, lane = tid & 31;
    const int g = lane >> 2, tg = lane & 3;
    const int qt0 = (gridDim.x - 1 - blockIdx.x) * 128;   // heavy-first
    const int h = blockIdx.y, b = blockIdx.z;

    const __half* qbase = qkv + (size_t)(b * T_ + qt0) * C3_ + h * HS_;
    const __half* kbase = qkv + (size_t)b * T_ * C3_ + C_  + h * HS_;
    const __half* vbase = qkv + (size_t)b * T_ * C3_ + 2*C_ + h * HS_;

    // stage Q tile (128x64 half), pre-scaled by log2(e)/8
    {
        int r = tid >> 1, c = (tid & 1) * 32;
        const __half2 s8 = __float2half2_rn(0.1803368801f);   // log2(e)/8
        #pragma unroll
        for (int i = 0; i < 4; i++) {
            __half2 v[4];
            *(uint4*)v = *(const uint4*)(qbase + (size_t)r * C3_ + c + i * 8);
            #pragma unroll
            for (int j = 0; j < 4; j++) v[j] = __hmul2(v[j], s8);
            *(uint4*)(Qs + r * AQSTR + c + i * 8) = *(uint4*)v;
        }
    }

    const int m0 = wid * 16;
    const int r0 = qt0 + m0 + g;
    const int my_max = qt0 + m0 + 15;
    const int ntiles = (qt0 + 128) >> 6;
    const int lrow = lane & 15;
    const int lcol = (lane >> 4) << 3;
    const uint32_t ONE2 = 0x3C003C00u;    // half2(1, 1)

    auto loadKV = [&](int s, int s0) {
        const __half* kp = kbase + (size_t)s0 * C3_;
        const __half* vp = vbase + (size_t)s0 * C3_;
        __half* Kd = Ks + s * 64 * AKSTR;
        __half* Vd = Vs + s * 64 * AKSTR;
        #pragma unroll
        for (int i = 0; i < 2; i++) {
            int idx = tid + (i << 8);           // 512 chunks of 16B per matrix
            int r = idx >> 3, c8 = (idx & 7) * 8;
            uint32_t dk = smem_u32(Kd + r * AKSTR + c8);
            asm volatile("cp.async.cg.shared.global [%0], [%1], 16;"
                         :: "r"(dk), "l"(kp + (size_t)r * C3_ + c8));
            uint32_t dv = smem_u32(Vd + r * AKSTR + c8);
            asm volatile("cp.async.cg.shared.global [%0], [%1], 16;"
                         :: "r"(dv), "l"(vp + (size_t)r * C3_ + c8));
        }
        asm volatile("cp.async.commit_group;");
    };

    loadKV(0, 0);
    __syncthreads();      // Q staging visible

    uint32_t qf[4][4];
    #pragma unroll
    for (int kc = 0; kc < 4; kc++)
        ldm_x4(qf[kc], smem_u32(Qs + (m0 + lrow) * AQSTR + kc * 16 + lcol));

    float mrow0 = -INFINITY, mrow1 = -INFINITY, lrow0s = 0.f, lrow1s = 0.f;
    float oacc[8][4];
    #pragma unroll
    for (int j = 0; j < 8; j++)
        #pragma unroll
        for (int r = 0; r < 4; r++) oacc[j][r] = 0.f;

    for (int t = 0; t < ntiles; t++) {
        const int s0 = t * 64;
        asm volatile("cp.async.wait_group 0;");
        __syncthreads();
        if (t + 1 < ntiles) loadKV((t + 1) & 1, s0 + 64);

        if (s0 <= my_max) {
            const __half* Kt = Ks + (t & 1) * 64 * AKSTR;
            const __half* Vt = Vs + (t & 1) * 64 * AKSTR;

            float sf[8][4];
            #pragma unroll
            for (int j = 0; j < 8; j++)
                #pragma unroll
                for (int r = 0; r < 4; r++) sf[j][r] = 0.f;
            #pragma unroll
            for (int kc = 0; kc < 4; kc++) {
                #pragma unroll
                for (int jb = 0; jb < 4; jb++) {
                    uint32_t kf[4];
                    ldm_x4(kf, smem_u32(Kt + (jb * 16 + lrow) * AKSTR + kc * 16 + lcol));
                    mma_fp16_2(sf[2*jb],   qf[kc], kf[0], kf[2]);
                    mma_fp16_2(sf[2*jb+1], qf[kc], kf[1], kf[3]);
                }
            }

            if (s0 + 63 > qt0 + m0) {
                #pragma unroll
                for (int j = 0; j < 8; j++) {
                    int c0 = s0 + j * 8 + 2 * tg, c1 = c0 + 1;
                    if (c0 > r0)     sf[j][0] = -INFINITY;
                    if (c1 > r0)     sf[j][1] = -INFINITY;
                    if (c0 > r0 + 8) sf[j][2] = -INFINITY;
                    if (c1 > r0 + 8) sf[j][3] = -INFINITY;
                }
            }

            float mx0 = -INFINITY, mx1 = -INFINITY;
            #pragma unroll
            for (int j = 0; j < 8; j++) {
                mx0 = fmaxf(mx0, fmaxf(sf[j][0], sf[j][1]));
                mx1 = fmaxf(mx1, fmaxf(sf[j][2], sf[j][3]));
            }
            mx0 = fmaxf(mx0, __shfl_xor_sync(0xffffffffu, mx0, 1));
            mx0 = fmaxf(mx0, __shfl_xor_sync(0xffffffffu, mx0, 2));
            mx1 = fmaxf(mx1, __shfl_xor_sync(0xffffffffu, mx1, 1));
            mx1 = fmaxf(mx1, __shfl_xor_sync(0xffffffffu, mx1, 2));

            float mn0 = fmaxf(mrow0, mx0), mn1 = fmaxf(mrow1, mx1);
            float corr0 = exp2f(mrow0 - mn0), corr1 = exp2f(mrow1 - mn1);
            mrow0 = mn0; mrow1 = mn1;

            uint32_t pj[8][2];
            #pragma unroll
            for (int j = 0; j < 8; j++) {
                __half2 e0 = h2exp2(__floats2half2_rn(sf[j][0] - mn0, sf[j][1] - mn0));
                __half2 e1 = h2exp2(__floats2half2_rn(sf[j][2] - mn1, sf[j][3] - mn1));
                pj[j][0] = *reinterpret_cast<uint32_t*>(&e0);
                pj[j][1] = *reinterpret_cast<uint32_t*>(&e1);
            }

            #pragma unroll
            for (int j = 0; j < 8; j++) {
                oacc[j][0] *= corr0; oacc[j][1] *= corr0;
                oacc[j][2] *= corr1; oacc[j][3] *= corr1;
            }

            float lacc[4] = {0.f, 0.f, 0.f, 0.f};
            #pragma unroll
            for (int kk = 0; kk < 4; kk++) {
                uint32_t ap[4] = { pj[2*kk][0], pj[2*kk][1],
                                   pj[2*kk+1][0], pj[2*kk+1][1] };
                mma_fp16_2(lacc, ap, ONE2, ONE2);
                #pragma unroll
                for (int db = 0; db < 4; db++) {
                    uint32_t vf[4];
                    ldm_x4_t(vf, smem_u32(Vt + (kk * 16 + lrow) * AKSTR + db * 16 + lcol));
                    mma_fp16_2(oacc[2*db],   ap, vf[0], vf[1]);
                    mma_fp16_2(oacc[2*db+1], ap, vf[2], vf[3]);
                }
            }
            lrow0s = lrow0s * corr0 + lacc[0];
            lrow1s = lrow1s * corr1 + lacc[2];
        }
    }

    float inv0 = 1.f / lrow0s;
    float inv1 = 1.f / lrow1s;
    __half* ob0 = o + ((size_t)(b * T_ + r0)) * C_ + h * HS_;
    __half* ob1 = ob0 + (size_t)8 * C_;
    #pragma unroll
    for (int j = 0; j < 8; j++) {
        int col = j * 8 + 2 * tg;
        *(__half2*)(ob0 + col) = __floats2half2_rn(oacc[j][0] * inv0, oacc[j][1] * inv0);
        *(__half2*)(ob1 + col) = __floats2half2_rn(oacc[j][2] * inv1, oacc[j][3] * inv1);
    }
}

// ---------------- launch ----------------
extern "C" void kernel_launch(void* const* d_in, const int* in_sizes, int n_in,
                              void* d_out, int out_size)
{
    const float* x     = (const float*)d_in[0];
    const float* Wq    = (const float*)d_in[1];
    const float* Wk    = (const float*)d_in[2];
    const float* Wv    = (const float*)d_in[3];
    const float* Wproj = (const float*)d_in[4];
    const float* bproj = (const float*)d_in[5];
    const float* W1    = (const float*)d_in[6];
    const float* b1    = (const float*)d_in[7];
    const float* W2    = (const float*)d_in[8];
    const float* b2    = (const float*)d_in[9];
    const float* ln1g  = (const float*)d_in[10];
    const float* ln1b  = (const float*)d_in[11];
    const float* ln2g  = (const float*)d_in[12];
    const float* ln2b  = (const float*)d_in[13];
    float* out = (float*)d_out;

    __half *h, *qkv, *ob, *ff, *wqkv, *wp, *w1, *w2;
    float *x1;
    cudaGetSymbolAddress((void**)&h,    g_h);
    cudaGetSymbolAddress((void**)&qkv,  g_qkv);
    cudaGetSymbolAddress((void**)&ob,   g_o);
    cudaGetSymbolAddress((void**)&x1,   g_x1);
    cudaGetSymbolAddress((void**)&ff,   g_ff);
    cudaGetSymbolAddress((void**)&wqkv, g_wqkv);
    cudaGetSymbolAddress((void**)&wp,   g_wp);
    cudaGetSymbolAddress((void**)&w1,   g_w1);
    cudaGetSymbolAddress((void**)&w2,   g_w2);

    cudaFuncSetAttribute(gemm_fp16, cudaFuncAttributeMaxDynamicSharedMemorySize, HG_SMEM);
    cudaFuncSetAttribute(attn_h,    cudaFuncAttributeMaxDynamicSharedMemorySize, ATTN_SMEM);

    // 1. fused prep: LN1 + qkv repack + all weight transposes (one launch)
    prep_kernel<<<PREP_GRID, 256>>>(x, ln1g, ln1b, h,
                                    Wq, Wk, Wv, wqkv,
                                    Wproj, wp, W1, w1, W2, w2);

    // 2. fused QKV projection -> half
    gemm_fp16<<<dim3(M_/128, C3_/128), 256, HG_SMEM>>>(h, wqkv, qkv, M_, C3_, C_,
                                                       nullptr, nullptr, 0, 2);

    // 3. fp16 causal flash attention -> half g_o
    dim3 ga(T_/128, H_, B_);
    attn_h<<<ga, 256, ATTN_SMEM>>>(qkv, ob);

    // 4. x1 = x + o @ Wproj + bproj  (fp32 out)
    gemm_fp16<<<dim3(M_/128, C_/128), 256, HG_SMEM>>>(ob, wp, x1, M_, C_, C_,
                                                      bproj, x, 0, 0);

    // 5. LN2 -> half
    ln_kernel<<<M_, 256>>>(x1, ln2g, ln2b, h);

    // 6. ff = relu(h @ W1 + b1) -> half
    gemm_fp16<<<dim3(M_/128, FF_/128), 256, HG_SMEM>>>(h, w1, ff, M_, FF_, C_,
                                                       b1, nullptr, 1, 2);

    // 7. out = x1 + ff @ W2 + b2  (final, fp32 out)
    gemm_fp16<<<dim3(M_/128, C_/128), 256, HG_SMEM>>>(ff, w2, out, M_, C_, FF_,
                                                      b2, x1, 0, 0);
}

// round 17
// speedup vs baseline: 1.0463x; 1.0055x over previous
#include <cuda_runtime.h>
#include <cuda_fp16.h>
#include <math.h>
#include <stdint.h>

// Problem constants
#define B_  4
#define T_  2048
#define C_  1024
#define C3_ 3072
#define H_  16
#define HS_ 64
#define FF_ 4096
#define M_  (B_*T_)     // 8192 rows
#define EPS_ 1e-5f

// ---------------- scratch (no dynamic alloc allowed) ----------------
__device__ __half g_h   [M_*C_];    // LN output (half)
__device__ __half g_qkv [M_*C3_];   // fused q|k|v (half), row stride 3072
__device__ __half g_o   [M_*C_];    // attention output (half)
__device__ __half g_x1  [M_*C_];    // x + attn_out @ Wproj + bproj (half)
__device__ __half g_ff  [M_*FF_];   // relu(h2 @ W1 + b1) (half)
__device__ __half g_wqkv[C3_*C_];   // repacked+transposed [3C, C] qkv weight (half)
__device__ __half g_wp  [C_*C_];    // transposed Wproj [N,K] (half)
__device__ __half g_w1  [FF_*C_];   // transposed W1 [4096,1024] (half)
__device__ __half g_w2  [C_*FF_];   // transposed W2 [1024,4096] (half)

// fp16 mma
__device__ __forceinline__ void mma_fp16(float* c, const uint32_t* a, const uint32_t* b) {
    asm volatile("mma.sync.aligned.m16n8k16.row.col.f32.f16.f16.f32 "
        "{%0,%1,%2,%3}, {%4,%5,%6,%7}, {%8,%9}, {%0,%1,%2,%3};"
        : "+f"(c[0]), "+f"(c[1]), "+f"(c[2]), "+f"(c[3])
        : "r"(a[0]), "r"(a[1]), "r"(a[2]), "r"(a[3]), "r"(b[0]), "r"(b[1]));
}
__device__ __forceinline__ void mma_fp16_2(float* c, const uint32_t* a,
                                           uint32_t b0, uint32_t b1) {
    asm volatile("mma.sync.aligned.m16n8k16.row.col.f32.f16.f16.f32 "
        "{%0,%1,%2,%3}, {%4,%5,%6,%7}, {%8,%9}, {%0,%1,%2,%3};"
        : "+f"(c[0]), "+f"(c[1]), "+f"(c[2]), "+f"(c[3])
        : "r"(a[0]), "r"(a[1]), "r"(a[2]), "r"(a[3]), "r"(b0), "r"(b1));
}
__device__ __forceinline__ void ldm_x4(uint32_t* r, uint32_t addr) {
    asm volatile("ldmatrix.sync.aligned.m8n8.x4.shared.b16 {%0,%1,%2,%3}, [%4];"
        : "=r"(r[0]), "=r"(r[1]), "=r"(r[2]), "=r"(r[3]) : "r"(addr));
}
__device__ __forceinline__ void ldm_x4_t(uint32_t* r, uint32_t addr) {
    asm volatile("ldmatrix.sync.aligned.m8n8.x4.trans.shared.b16 {%0,%1,%2,%3}, [%4];"
        : "=r"(r[0]), "=r"(r[1]), "=r"(r[2]), "=r"(r[3]) : "r"(addr));
}
__device__ __forceinline__ uint32_t smem_u32(const void* p) {
    return (uint32_t)__cvta_generic_to_shared(p);
}

// ---------------- fused prep mega-kernel ----------------
#define PREP_LN   8192
#define PREP_RP   12288
#define PREP_TP   1024
#define PREP_T1   4096
#define PREP_T2   4096
#define PREP_GRID (PREP_LN + PREP_RP + PREP_TP + PREP_T1 + PREP_T2)

__device__ __forceinline__ void do_ln_row(const float* __restrict__ xr,
                                          const float* __restrict__ g,
                                          const float* __restrict__ b,
                                          __half* __restrict__ yr,
                                          float* ws, float* ws2)
{
    int tid = threadIdx.x;
    int wid = tid >> 5, lane = tid & 31;

    float4 v = *(const float4*)(xr + tid * 4);
    float s  = v.x + v.y + v.z + v.w;
    float s2 = v.x * v.x + v.y * v.y + v.z * v.z + v.w * v.w;
    #pragma unroll
    for (int off = 16; off > 0; off >>= 1) {
        s  += __shfl_xor_sync(0xffffffffu, s,  off);
        s2 += __shfl_xor_sync(0xffffffffu, s2, off);
    }
    if (lane == 0) { ws[wid] = s; ws2[wid] = s2; }
    __syncthreads();
    if (wid == 0) {
        float a  = (lane < 8) ? ws[lane]  : 0.f;
        float a2 = (lane < 8) ? ws2[lane] : 0.f;
        #pragma unroll
        for (int off = 4; off > 0; off >>= 1) {
            a  += __shfl_xor_sync(0xffffffffu, a,  off);
            a2 += __shfl_xor_sync(0xffffffffu, a2, off);
        }
        if (lane == 0) { ws[0] = a; ws2[0] = a2; }
    }
    __syncthreads();
    float mean = ws[0] * (1.0f / C_);
    float var  = ws2[0] * (1.0f / C_) - mean * mean;
    float rstd = rsqrtf(var + EPS_);

    const float4 gv = *(const float4*)(g + tid * 4);
    const float4 bv = *(const float4*)(b + tid * 4);
    __half2 h0 = __floats2half2_rn((v.x - mean) * rstd * gv.x + bv.x,
                                   (v.y - mean) * rstd * gv.y + bv.y);
    __half2 h1 = __floats2half2_rn((v.z - mean) * rstd * gv.z + bv.z,
                                   (v.w - mean) * rstd * gv.w + bv.w);
    *(__half2*)(yr + tid * 4)     = h0;
    *(__half2*)(yr + tid * 4 + 2) = h1;
}

__device__ __forceinline__ void do_transpose32(const float* __restrict__ S,
                                               __half* __restrict__ D,
                                               int R, int Cc, int bx, int by,
                                               float* t /* 32x33 */)
{
    int tid = threadIdx.x;
    int x = tid & 31, y = tid >> 5;   // y in 0..7
    #pragma unroll
    for (int i = 0; i < 32; i += 8)
        t[(y + i) * 33 + x] = S[(size_t)(by * 32 + y + i) * Cc + bx * 32 + x];
    __syncthreads();
    #pragma unroll
    for (int i = 0; i < 32; i += 8)
        D[(size_t)(bx * 32 + y + i) * R + by * 32 + x] =
            __float2half_rn(t[x * 33 + (y + i)]);
}

__global__ __launch_bounds__(256) void prep_kernel(
    const float* __restrict__ x,
    const float* __restrict__ ln1g, const float* __restrict__ ln1b,
    __half* __restrict__ h,
    const float* __restrict__ Wq, const float* __restrict__ Wk,
    const float* __restrict__ Wv, __half* __restrict__ wqkv,
    const float* __restrict__ Wproj, __half* __restrict__ wp,
    const float* __restrict__ W1, __half* __restrict__ w1,
    const float* __restrict__ W2, __half* __restrict__ w2)
{
    __shared__ float tbuf[32 * 33];
    int bidx = blockIdx.x;

    if (bidx < PREP_LN) {
        do_ln_row(x + (size_t)bidx * C_, ln1g, ln1b, h + (size_t)bidx * C_,
                  tbuf, tbuf + 8);
        return;
    }
    bidx -= PREP_LN;
    if (bidx < PREP_RP) {
        int idx = bidx * 256 + threadIdx.x;   // idx = n*C + c
        int n = idx >> 10;
        int c = idx & (C_ - 1);
        int sec = n >> 10;
        int nn = n & (C_ - 1);
        int hh = nn >> 6;
        int d = nn & (HS_ - 1);
        const float* W = (sec == 0) ? Wq : (sec == 1) ? Wk : Wv;
        wqkv[idx] = __float2half_rn(W[(size_t)hh * C_ * HS_ + (size_t)c * HS_ + d]);
        return;
    }
    bidx -= PREP_RP;
    if (bidx < PREP_TP) {
        do_transpose32(Wproj, wp, C_, C_, bidx & 31, bidx >> 5, tbuf);
        return;
    }
    bidx -= PREP_TP;
    if (bidx < PREP_T1) {
        do_transpose32(W1, w1, C_, FF_, bidx & 127, bidx >> 7, tbuf);
        return;
    }
    bidx -= PREP_T1;
    {
        do_transpose32(W2, w2, FF_, C_, bidx & 31, bidx >> 5, tbuf);
    }
}

// ---------------- LayerNorm, half input (LN2) ----------------
__global__ __launch_bounds__(256) void ln_kernel_h(const __half* __restrict__ x,
                                                   const float* __restrict__ g,
                                                   const float* __restrict__ b,
                                                   __half* __restrict__ y)
{
    __shared__ float ws[8], ws2[8];
    int row = blockIdx.x;
    const __half* xr = x + (size_t)row * C_;
    __half* yr = y + (size_t)row * C_;
    int tid = threadIdx.x;
    int wid = tid >> 5, lane = tid & 31;

    __half2 hv[2];
    *(uint2*)hv = *(const uint2*)(xr + tid * 4);
    float2 f0 = __half22float2(hv[0]);
    float2 f1 = __half22float2(hv[1]);
    float s  = f0.x + f0.y + f1.x + f1.y;
    float s2 = f0.x * f0.x + f0.y * f0.y + f1.x * f1.x + f1.y * f1.y;
    #pragma unroll
    for (int off = 16; off > 0; off >>= 1) {
        s  += __shfl_xor_sync(0xffffffffu, s,  off);
        s2 += __shfl_xor_sync(0xffffffffu, s2, off);
    }
    if (lane == 0) { ws[wid] = s; ws2[wid] = s2; }
    __syncthreads();
    if (wid == 0) {
        float a  = (lane < 8) ? ws[lane]  : 0.f;
        float a2 = (lane < 8) ? ws2[lane] : 0.f;
        #pragma unroll
        for (int off = 4; off > 0; off >>= 1) {
            a  += __shfl_xor_sync(0xffffffffu, a,  off);
            a2 += __shfl_xor_sync(0xffffffffu, a2, off);
        }
        if (lane == 0) { ws[0] = a; ws2[0] = a2; }
    }
    __syncthreads();
    float mean = ws[0] * (1.0f / C_);
    float var  = ws2[0] * (1.0f / C_) - mean * mean;
    float rstd = rsqrtf(var + EPS_);

    const float4 gv = *(const float4*)(g + tid * 4);
    const float4 bv = *(const float4*)(b + tid * 4);
    __half2 o0 = __floats2half2_rn((f0.x - mean) * rstd * gv.x + bv.x,
                                   (f0.y - mean) * rstd * gv.y + bv.y);
    __half2 o1 = __floats2half2_rn((f1.x - mean) * rstd * gv.z + bv.z,
                                   (f1.y - mean) * rstd * gv.w + bv.w);
    *(__half2*)(yr + tid * 4)     = o0;
    *(__half2*)(yr + tid * 4 + 2) = o1;
}

// ---------------- fp16 mma.sync GEMM, BK=64, 2-stage ----------------
// C[M,N] = A[M,K] @ Bt[N,K]^T  (+bias)(+res)(relu)
// out_mode: 0 = fp32 out, 2 = half out.  res_half: residual dtype.
#define HSTR 72
#define HG_STAGE (2*128*HSTR)          // halves per stage (A+B) = 18432
#define HG_SMEM  (2*HG_STAGE*2)        // 73728 bytes

__global__ __launch_bounds__(256, 2) void gemm_fp16(const __half* __restrict__ A,
                                                    const __half* __restrict__ Bt,
                                                    void* __restrict__ Cm,
                                                    int Mn, int Nn, int Kn,
                                                    const float* __restrict__ bias,
                                                    const void* __restrict__ res,
                                                    int res_half,
                                                    int relu, int out_mode)
{
    extern __shared__ __half smh[];
    const int tid = threadIdx.x;
    const int wid = tid >> 5, lane = tid & 31;
    const int g = lane >> 2, tg = lane & 3;
    const int warp_m = wid >> 2;       // 0..1  (64 rows)
    const int warp_n = wid & 3;        // 0..3  (32 cols)
    const int bm = blockIdx.x * 128;
    const int bn = blockIdx.y * 128;

    const int a_row  = lane & 15;
    const int a_koff = (lane >> 4) << 3;
    const int b_row  = ((lane >> 4) << 3) + (lane & 7);
    const int b_koff = ((lane >> 3) & 1) << 3;

    float acc[4][4][4];
    #pragma unroll
    for (int mi = 0; mi < 4; mi++)
        #pragma unroll
        for (int ni = 0; ni < 4; ni++)
            #pragma unroll
            for (int r = 0; r < 4; r++) acc[mi][ni][r] = 0.f;

    auto fill = [&](int s, int kt) {
        const int k0 = kt << 6;
        __half* As = smh + s * HG_STAGE;
        __half* Bs = As + 128 * HSTR;
        #pragma unroll
        for (int i = 0; i < 4; i++) {
            int idx = tid + (i << 8);          // 1024 chunks of 16B per matrix
            int r = idx >> 3, c8 = (idx & 7) << 3;
            uint32_t da = smem_u32(As + r * HSTR + c8);
            asm volatile("cp.async.cg.shared.global [%0], [%1], 16;"
                         :: "r"(da), "l"(A + (size_t)(bm + r) * Kn + k0 + c8));
            uint32_t db = smem_u32(Bs + r * HSTR + c8);
            asm volatile("cp.async.cg.shared.global [%0], [%1], 16;"
                         :: "r"(db), "l"(Bt + (size_t)(bn + r) * Kn + k0 + c8));
        }
        asm volatile("cp.async.commit_group;");
    };

    const int KT = Kn >> 6;
    fill(0, 0);

    for (int kt = 0; kt < KT; kt++) {
        asm volatile("cp.async.wait_group 0;");
        __syncthreads();
        if (kt + 1 < KT) fill((kt + 1) & 1, kt + 1);

        const __half* As = smh + (kt & 1) * HG_STAGE;
        const __half* Bs = As + 128 * HSTR;

        #pragma unroll
        for (int ks = 0; ks < 4; ks++) {
            const int kb0 = ks * 16;
            uint32_t af[4][4], bq[2][4];
            #pragma unroll
            for (int mi = 0; mi < 4; mi++)
                ldm_x4(af[mi], smem_u32(As + (warp_m * 64 + mi * 16 + a_row) * HSTR
                                           + kb0 + a_koff));
            #pragma unroll
            for (int np = 0; np < 2; np++)
                ldm_x4(bq[np], smem_u32(Bs + (warp_n * 32 + np * 16 + b_row) * HSTR
                                           + kb0 + b_koff));
            #pragma unroll
            for (int mi = 0; mi < 4; mi++)
                #pragma unroll
                for (int ni = 0; ni < 4; ni++)
                    mma_fp16(acc[mi][ni], af[mi], &bq[ni >> 1][(ni & 1) * 2]);
        }
        // no trailing sync: next iteration's top __syncthreads orders
        // this compute before fill overwrites the other stage.
    }

    #pragma unroll
    for (int mi = 0; mi < 4; mi++) {
        #pragma unroll
        for (int ni = 0; ni < 4; ni++) {
            int row0 = bm + warp_m * 64 + mi * 16 + g;
            int col  = bn + warp_n * 32 + ni * 8 + tg * 2;
            float bx = 0.f, by = 0.f;
            if (bias) { bx = bias[col]; by = bias[col + 1]; }
            #pragma unroll
            for (int half_ = 0; half_ < 2; half_++) {
                int row = row0 + half_ * 8;
                float v0 = acc[mi][ni][half_ * 2 + 0] + bx;
                float v1 = acc[mi][ni][half_ * 2 + 1] + by;
                if (res) {
                    if (res_half) {
                        __half2 rv = *(const __half2*)((const __half*)res
                                        + (size_t)row * Nn + col);
                        float2 rf = __half22float2(rv);
                        v0 += rf.x; v1 += rf.y;
                    } else {
                        const float* rp = (const float*)res + (size_t)row * Nn + col;
                        v0 += rp[0]; v1 += rp[1];
                    }
                }
                if (relu) { v0 = fmaxf(v0, 0.f); v1 = fmaxf(v1, 0.f); }
                if (out_mode == 2) {
                    __half2 hv = __floats2half2_rn(v0, v1);
                    *(__half2*)((__half*)Cm + (size_t)row * Nn + col) = hv;
                } else {
                    *(float2*)((float*)Cm + (size_t)row * Nn + col) = make_float2(v0, v1);
                }
            }
        }
    }
}

// ---------------- fp16 tensor-core flash attention (heavy-first order) ----------
#define AKSTR 72
#define AQSTR 72
#define ATTN_SMEM ((4*64*AKSTR + 128*AQSTR)*2)   // 55296 bytes

__global__ __launch_bounds__(256, 2) void attn_h(const __half* __restrict__ qkv,
                                                 __half* __restrict__ o)
{
    extern __shared__ __half smha[];
    __half* Ks = smha;                    // 2 stages 64 x AKSTR
    __half* Vs = smha + 2*64*AKSTR;       // 2 stages 64 x AKSTR
    __half* Qs = Vs + 2*64*AKSTR;         // 128 x AQSTR (Q, pre-scaled)

    const int tid = threadIdx.x, wid = tid >> 5, lane = tid & 31;
    const int g = lane >> 2, tg = lane & 3;
    const int qt0 = (gridDim.x - 1 - blockIdx.x) * 128;   // heavy-first
    const int h = blockIdx.y, b = blockIdx.z;

    const __half* qbase = qkv + (size_t)(b * T_ + qt0) * C3_ + h * HS_;
    const __half* kbase = qkv + (size_t)b * T_ * C3_ + C_  + h * HS_;
    const __half* vbase = qkv + (size_t)b * T_ * C3_ + 2*C_ + h * HS_;

    // stage Q tile (128x64 half), pre-scaled by log2(e)/8
    {
        int r = tid >> 1, c = (tid & 1) * 32;
        const __half2 s8 = __float2half2_rn(0.1803368801f);   // log2(e)/8
        #pragma unroll
        for (int i = 0; i < 4; i++) {
            __half2 v[4];
            *(uint4*)v = *(const uint4*)(qbase + (size_t)r * C3_ + c + i * 8);
            #pragma unroll
            for (int j = 0; j < 4; j++) v[j] = __hmul2(v[j], s8);
            *(uint4*)(Qs + r * AQSTR + c + i * 8) = *(uint4*)v;
        }
    }

    const int m0 = wid * 16;
    const int r0 = qt0 + m0 + g;
    const int my_max = qt0 + m0 + 15;
    const int ntiles = (qt0 + 128) >> 6;
    const int lrow = lane & 15;
    const int lcol = (lane >> 4) << 3;
    const uint32_t ONE2 = 0x3C003C00u;    // half2(1, 1)

    auto loadKV = [&](int s, int s0) {
        const __half* kp = kbase + (size_t)s0 * C3_;
        const __half* vp = vbase + (size_t)s0 * C3_;
        __half* Kd = Ks + s * 64 * AKSTR;
        __half* Vd = Vs + s * 64 * AKSTR;
        #pragma unroll
        for (int i = 0; i < 2; i++) {
            int idx = tid + (i << 8);           // 512 chunks of 16B per matrix
            int r = idx >> 3, c8 = (idx & 7) * 8;
            uint32_t dk = smem_u32(Kd + r * AKSTR + c8);
            asm volatile("cp.async.cg.shared.global [%0], [%1], 16;"
                         :: "r"(dk), "l"(kp + (size_t)r * C3_ + c8));
            uint32_t dv = smem_u32(Vd + r * AKSTR + c8);
            asm volatile("cp.async.cg.shared.global [%0], [%1], 16;"
                         :: "r"(dv), "l"(vp + (size_t)r * C3_ + c8));
        }
        asm volatile("cp.async.commit_group;");
    };

    loadKV(0, 0);
    __syncthreads();      // Q staging visible

    uint32_t qf[4][4];
    #pragma unroll
    for (int kc = 0; kc < 4; kc++)
        ldm_x4(qf[kc], smem_u32(Qs + (m0 + lrow) * AQSTR + kc * 16 + lcol));

    float mrow0 = -INFINITY, mrow1 = -INFINITY, lrow0s = 0.f, lrow1s = 0.f;
    float oacc[8][4];
    #pragma unroll
    for (int j = 0; j < 8; j++)
        #pragma unroll
        for (int r = 0; r < 4; r++) oacc[j][r] = 0.f;

    for (int t = 0; t < ntiles; t++) {
        const int s0 = t * 64;
        asm volatile("cp.async.wait_group 0;");
        __syncthreads();
        if (t + 1 < ntiles) loadKV((t + 1) & 1, s0 + 64);

        if (s0 <= my_max) {
            const __half* Kt = Ks + (t & 1) * 64 * AKSTR;
            const __half* Vt = Vs + (t & 1) * 64 * AKSTR;

            float sf[8][4];
            #pragma unroll
            for (int j = 0; j < 8; j++)
                #pragma unroll
                for (int r = 0; r < 4; r++) sf[j][r] = 0.f;
            #pragma unroll
            for (int kc = 0; kc < 4; kc++) {
                #pragma unroll
                for (int jb = 0; jb < 4; jb++) {
                    uint32_t kf[4];
                    ldm_x4(kf, smem_u32(Kt + (jb * 16 + lrow) * AKSTR + kc * 16 + lcol));
                    mma_fp16_2(sf[2*jb],   qf[kc], kf[0], kf[2]);
                    mma_fp16_2(sf[2*jb+1], qf[kc], kf[1], kf[3]);
                }
            }

            if (s0 + 63 > qt0 + m0) {
                #pragma unroll
                for (int j = 0; j < 8; j++) {
                    int c0 = s0 + j * 8 + 2 * tg, c1 = c0 + 1;
                    if (c0 > r0)     sf[j][0] = -INFINITY;
                    if (c1 > r0)     sf[j][1] = -INFINITY;
                    if (c0 > r0 + 8) sf[j][2] = -INFINITY;
                    if (c1 > r0 + 8) sf[j][3] = -INFINITY;
                }
            }

            float mx0 = -INFINITY, mx1 = -INFINITY;
            #pragma unroll
            for (int j = 0; j < 8; j++) {
                mx0 = fmaxf(mx0, fmaxf(sf[j][0], sf[j][1]));
                mx1 = fmaxf(mx1, fmaxf(sf[j][2], sf[j][3]));
            }
            mx0 = fmaxf(mx0, __shfl_xor_sync(0xffffffffu, mx0, 1));
            mx0 = fmaxf(mx0, __shfl_xor_sync(0xffffffffu, mx0, 2));
            mx1 = fmaxf(mx1, __shfl_xor_sync(0xffffffffu, mx1, 1));
            mx1 = fmaxf(mx1, __shfl_xor_sync(0xffffffffu, mx1, 2));

            float mn0 = fmaxf(mrow0, mx0), mn1 = fmaxf(mrow1, mx1);
            float corr0 = exp2f(mrow0 - mn0), corr1 = exp2f(mrow1 - mn1);
            mrow0 = mn0; mrow1 = mn1;

            uint32_t pj[8][2];
            #pragma unroll
            for (int j = 0; j < 8; j++) {
                __half2 e0 = h2exp2(__floats2half2_rn(sf[j][0] - mn0, sf[j][1] - mn0));
                __half2 e1 = h2exp2(__floats2half2_rn(sf[j][2] - mn1, sf[j][3] - mn1));
                pj[j][0] = *reinterpret_cast<uint32_t*>(&e0);
                pj[j][1] = *reinterpret_cast<uint32_t*>(&e1);
            }

            #pragma unroll
            for (int j = 0; j < 8; j++) {
                oacc[j][0] *= corr0; oacc[j][1] *= corr0;
                oacc[j][2] *= corr1; oacc[j][3] *= corr1;
            }

            float lacc[4] = {0.f, 0.f, 0.f, 0.f};
            #pragma unroll
            for (int kk = 0; kk < 4; kk++) {
                uint32_t ap[4] = { pj[2*kk][0], pj[2*kk][1],
                                   pj[2*kk+1][0], pj[2*kk+1][1] };
                mma_fp16_2(lacc, ap, ONE2, ONE2);
                #pragma unroll
                for (int db = 0; db < 4; db++) {
                    uint32_t vf[4];
                    ldm_x4_t(vf, smem_u32(Vt + (kk * 16 + lrow) * AKSTR + db * 16 + lcol));
                    mma_fp16_2(oacc[2*db],   ap, vf[0], vf[1]);
                    mma_fp16_2(oacc[2*db+1], ap, vf[2], vf[3]);
                }
            }
            lrow0s = lrow0s * corr0 + lacc[0];
            lrow1s = lrow1s * corr1 + lacc[2];
        }
    }

    float inv0 = 1.f / lrow0s;
    float inv1 = 1.f / lrow1s;
    __half* ob0 = o + ((size_t)(b * T_ + r0)) * C_ + h * HS_;
    __half* ob1 = ob0 + (size_t)8 * C_;
    #pragma unroll
    for (int j = 0; j < 8; j++) {
        int col = j * 8 + 2 * tg;
        *(__half2*)(ob0 + col) = __floats2half2_rn(oacc[j][0] * inv0, oacc[j][1] * inv0);
        *(__half2*)(ob1 + col) = __floats2half2_rn(oacc[j][2] * inv1, oacc[j][3] * inv1);
    }
}

// ---------------- launch ----------------
extern "C" void kernel_launch(void* const* d_in, const int* in_sizes, int n_in,
                              void* d_out, int out_size)
{
    const float* x     = (const float*)d_in[0];
    const float* Wq    = (const float*)d_in[1];
    const float* Wk    = (const float*)d_in[2];
    const float* Wv    = (const float*)d_in[3];
    const float* Wproj = (const float*)d_in[4];
    const float* bproj = (const float*)d_in[5];
    const float* W1    = (const float*)d_in[6];
    const float* b1    = (const float*)d_in[7];
    const float* W2    = (const float*)d_in[8];
    const float* b2    = (const float*)d_in[9];
    const float* ln1g  = (const float*)d_in[10];
    const float* ln1b  = (const float*)d_in[11];
    const float* ln2g  = (const float*)d_in[12];
    const float* ln2b  = (const float*)d_in[13];
    float* out = (float*)d_out;

    __half *h, *qkv, *ob, *x1, *ff, *wqkv, *wp, *w1, *w2;
    cudaGetSymbolAddress((void**)&h,    g_h);
    cudaGetSymbolAddress((void**)&qkv,  g_qkv);
    cudaGetSymbolAddress((void**)&ob,   g_o);
    cudaGetSymbolAddress((void**)&x1,   g_x1);
    cudaGetSymbolAddress((void**)&ff,   g_ff);
    cudaGetSymbolAddress((void**)&wqkv, g_wqkv);
    cudaGetSymbolAddress((void**)&wp,   g_wp);
    cudaGetSymbolAddress((void**)&w1,   g_w1);
    cudaGetSymbolAddress((void**)&w2,   g_w2);

    cudaFuncSetAttribute(gemm_fp16, cudaFuncAttributeMaxDynamicSharedMemorySize, HG_SMEM);
    cudaFuncSetAttribute(attn_h,    cudaFuncAttributeMaxDynamicSharedMemorySize, ATTN_SMEM);

    // 1. fused prep: LN1 + qkv repack + all weight transposes (one launch)
    prep_kernel<<<PREP_GRID, 256>>>(x, ln1g, ln1b, h,
                                    Wq, Wk, Wv, wqkv,
                                    Wproj, wp, W1, w1, W2, w2);

    // 2. fused QKV projection -> half
    gemm_fp16<<<dim3(M_/128, C3_/128), 256, HG_SMEM>>>(h, wqkv, qkv, M_, C3_, C_,
                                                       nullptr, nullptr, 0, 0, 2);

    // 3. fp16 causal flash attention -> half g_o
    dim3 ga(T_/128, H_, B_);
    attn_h<<<ga, 256, ATTN_SMEM>>>(qkv, ob);

    // 4. x1 = x + o @ Wproj + bproj  (half out; fp32 residual x)
    gemm_fp16<<<dim3(M_/128, C_/128), 256, HG_SMEM>>>(ob, wp, x1, M_, C_, C_,
                                                      bproj, x, 0, 0, 2);

    // 5. LN2 (half in) -> half
    ln_kernel_h<<<M_, 256>>>(x1, ln2g, ln2b, h);

    // 6. ff = relu(h @ W1 + b1) -> half
    gemm_fp16<<<dim3(M_/128, FF_/128), 256, HG_SMEM>>>(h, w1, ff, M_, FF_, C_,
                                                       b1, nullptr, 0, 1, 2);

    // 7. out = x1 + ff @ W2 + b2  (fp32 out; half residual x1)
    gemm_fp16<<<dim3(M_/128, C_/128), 256, HG_SMEM>>>(ff, w2, out, M_, C_, FF_,
                                                      b2, x1, 1, 0, 0);
}